// round 5
// baseline (speedup 1.0000x reference)
#include <cuda_runtime.h>
#include <cuda_bf16.h>
#include <math.h>

#define N_TOK  2048
#define DIMM   1024
#define NBATCH 2
#define NHEAD  16
#define DHEAD  64
#define BETA_V 0.125f

// Scratch (static device allocations — no cudaMalloc anywhere)
__device__ float g_qk[(size_t)(NBATCH * N_TOK) * (2 * DIMM)];  // 32 MB
__device__ float g_ao[(size_t)(NBATCH * N_TOK) * DIMM];        // 16 MB
__device__ float g_xr[(size_t)(NBATCH * N_TOK) * DIMM];        // 16 MB rounded x
__device__ float g_wqkr[(size_t)DIMM * (2 * DIMM)];            //  8 MB rounded W_qk
__device__ float g_wor[(size_t)DIMM * DIMM];                   //  4 MB rounded W_out

// ---------------------------------------------------------------------------
// helpers
// ---------------------------------------------------------------------------
__device__ __forceinline__ unsigned f2tf32(float x) {
    unsigned u;
    asm("cvt.rna.tf32.f32 %0, %1;" : "=r"(u) : "f"(x));
    return u;
}

__device__ __forceinline__ void mma_tf32(
    float& c0, float& c1, float& c2, float& c3,
    unsigned a0, unsigned a1, unsigned a2, unsigned a3,
    unsigned b0, unsigned b1)
{
    asm volatile(
        "mma.sync.aligned.m16n8k8.row.col.f32.tf32.tf32.f32 "
        "{%0,%1,%2,%3}, {%4,%5,%6,%7}, {%8,%9}, {%0,%1,%2,%3};"
        : "+f"(c0), "+f"(c1), "+f"(c2), "+f"(c3)
        : "r"(a0), "r"(a1), "r"(a2), "r"(a3), "r"(b0), "r"(b1));
}

__device__ __forceinline__ void cp_async16(void* smem, const void* gmem) {
    unsigned saddr = (unsigned)__cvta_generic_to_shared(smem);
    asm volatile("cp.async.cg.shared.global [%0], [%1], 16;"
                 :: "r"(saddr), "l"(gmem));
}

// ---------------------------------------------------------------------------
// Elementwise tf32 pre-round: dst = round_tf32(src). n4 = float4 count.
// ---------------------------------------------------------------------------
__global__ void __launch_bounds__(256) round_kernel(
    const float* __restrict__ src, float* __restrict__ dst, int n4)
{
    int i = blockIdx.x * 256 + threadIdx.x;
    if (i < n4) {
        float4 v = ((const float4*)src)[i];
        float4 o;
        o.x = __uint_as_float(f2tf32(v.x));
        o.y = __uint_as_float(f2tf32(v.y));
        o.z = __uint_as_float(f2tf32(v.z));
        o.w = __uint_as_float(f2tf32(v.w));
        ((float4*)dst)[i] = o;
    }
}

// ---------------------------------------------------------------------------
// tf32 GEMM, inputs PRE-ROUNDED to tf32. C = A @ B row-major.
// 128x128 tile, BK=16, 8 warps x (32x64), 3-stage cp.async pipeline.
// ROUND_OUT: round the fp32 result to tf32 at store (for downstream tf32 use).
// ---------------------------------------------------------------------------
#define AS_STR 20
#define BS_STR 136

template <bool ROUND_OUT>
__global__ void __launch_bounds__(256) tgemm_kernel(
    const float* __restrict__ A, const float* __restrict__ B,
    float* __restrict__ C, int M, int N, int K)
{
    __shared__ float As[3][128][AS_STR];
    __shared__ float Bs[3][16][BS_STR];

    const int tid  = threadIdx.x;
    const int w    = tid >> 5;
    const int lane = tid & 31;
    const int g    = lane >> 2;
    const int t    = lane & 3;
    const int wm   = (w & 3) * 32;
    const int wn   = (w >> 2) * 64;

    const int mbase = blockIdx.y * 128;
    const int nbase = blockIdx.x * 128;

    const int arow0 = tid >> 2,         acc0 = (tid & 3) * 4;
    const int arow1 = (tid + 256) >> 2, acc1 = ((tid + 256) & 3) * 4;
    const int brow0 = tid >> 5,         bcc0 = (tid & 31) * 4;
    const int brow1 = (tid + 256) >> 5, bcc1 = ((tid + 256) & 31) * 4;

    float acc[2][8][4];
#pragma unroll
    for (int mt = 0; mt < 2; mt++)
#pragma unroll
        for (int nt = 0; nt < 8; nt++)
#pragma unroll
            for (int j = 0; j < 4; j++) acc[mt][nt][j] = 0.f;

    const int NIT = K / 16;

#pragma unroll
    for (int s = 0; s < 2; s++) {
        const int k0 = s * 16;
        cp_async16(&As[s][arow0][acc0], A + (size_t)(mbase + arow0) * K + k0 + acc0);
        cp_async16(&As[s][arow1][acc1], A + (size_t)(mbase + arow1) * K + k0 + acc1);
        cp_async16(&Bs[s][brow0][bcc0], B + (size_t)(k0 + brow0) * N + nbase + bcc0);
        cp_async16(&Bs[s][brow1][bcc1], B + (size_t)(k0 + brow1) * N + nbase + bcc1);
        asm volatile("cp.async.commit_group;");
    }

    int buf = 0;
    for (int it = 0; it < NIT; it++) {
        if (it + 1 < NIT)
            asm volatile("cp.async.wait_group 1;");
        else
            asm volatile("cp.async.wait_group 0;");
        __syncthreads();

#pragma unroll
        for (int kc = 0; kc < 2; kc++) {
            unsigned af[2][4];
#pragma unroll
            for (int mt = 0; mt < 2; mt++) {
                const int m = wm + mt * 16;
                af[mt][0] = __float_as_uint(As[buf][m + g][kc * 8 + t]);
                af[mt][1] = __float_as_uint(As[buf][m + 8 + g][kc * 8 + t]);
                af[mt][2] = __float_as_uint(As[buf][m + g][kc * 8 + t + 4]);
                af[mt][3] = __float_as_uint(As[buf][m + 8 + g][kc * 8 + t + 4]);
            }
#pragma unroll
            for (int nt = 0; nt < 8; nt++) {
                unsigned b0 = __float_as_uint(Bs[buf][kc * 8 + t][wn + nt * 8 + g]);
                unsigned b1 = __float_as_uint(Bs[buf][kc * 8 + t + 4][wn + nt * 8 + g]);
                mma_tf32(acc[0][nt][0], acc[0][nt][1], acc[0][nt][2], acc[0][nt][3],
                         af[0][0], af[0][1], af[0][2], af[0][3], b0, b1);
                mma_tf32(acc[1][nt][0], acc[1][nt][1], acc[1][nt][2], acc[1][nt][3],
                         af[1][0], af[1][1], af[1][2], af[1][3], b0, b1);
            }
        }

        if (it + 2 < NIT) {
            const int k0 = (it + 2) * 16;
            const int nb = (it + 2) % 3;
            cp_async16(&As[nb][arow0][acc0], A + (size_t)(mbase + arow0) * K + k0 + acc0);
            cp_async16(&As[nb][arow1][acc1], A + (size_t)(mbase + arow1) * K + k0 + acc1);
            cp_async16(&Bs[nb][brow0][bcc0], B + (size_t)(k0 + brow0) * N + nbase + bcc0);
            cp_async16(&Bs[nb][brow1][bcc1], B + (size_t)(k0 + brow1) * N + nbase + bcc1);
            asm volatile("cp.async.commit_group;");
        }
        __syncthreads();
        buf = (buf + 1 == 3) ? 0 : buf + 1;
    }

#pragma unroll
    for (int mt = 0; mt < 2; mt++) {
        const int r0 = mbase + wm + mt * 16 + g;
#pragma unroll
        for (int nt = 0; nt < 8; nt++) {
            const int col = nbase + wn + nt * 8 + 2 * t;
            float v0 = acc[mt][nt][0], v1 = acc[mt][nt][1];
            float v2 = acc[mt][nt][2], v3 = acc[mt][nt][3];
            if (ROUND_OUT) {
                v0 = __uint_as_float(f2tf32(v0));
                v1 = __uint_as_float(f2tf32(v1));
                v2 = __uint_as_float(f2tf32(v2));
                v3 = __uint_as_float(f2tf32(v3));
            }
            *(float2*)(C + (size_t)r0 * N + col)       = make_float2(v0, v1);
            *(float2*)(C + (size_t)(r0 + 8) * N + col) = make_float2(v2, v3);
        }
    }
}

// ---------------------------------------------------------------------------
// Tensor-core causal flash attention; qk PRE-ROUNDED to tf32.
// 4 warps, 64 q-rows/block, cp.async double-buffered K tiles.
// Output written tf32-rounded (input to GEMM2).
// ---------------------------------------------------------------------------
__global__ void __launch_bounds__(128) attn_tc_kernel(
    const float* __restrict__ qk, float* __restrict__ out)
{
    const int qt = blockIdx.x, h = blockIdx.y, bb = blockIdx.z;
    const int tid  = threadIdx.x;
    const int w    = tid >> 5;
    const int lane = tid & 31;
    const int g    = lane >> 2;
    const int t    = lane & 3;

    __shared__ float Ks[2][64][68];

    const int qrow0 = bb * N_TOK + qt * 64 + w * 16;
    // qk is tf32-rounded; *0.125f (2^-3) is exact -> frags need no cvt.
    unsigned qf[8][4];
#pragma unroll
    for (int kc = 0; kc < 8; kc++) {
        const float* qp  = qk + (size_t)(qrow0 + g) * (2 * DIMM) + h * DHEAD + kc * 8;
        const float* qp8 = qp + (size_t)8 * (2 * DIMM);
        qf[kc][0] = __float_as_uint(qp[t]      * BETA_V);
        qf[kc][1] = __float_as_uint(qp8[t]     * BETA_V);
        qf[kc][2] = __float_as_uint(qp[t + 4]  * BETA_V);
        qf[kc][3] = __float_as_uint(qp8[t + 4] * BETA_V);
    }

    float o[8][4];
#pragma unroll
    for (int nt = 0; nt < 8; nt++)
#pragma unroll
        for (int j = 0; j < 4; j++) o[nt][j] = 0.f;
    float m0 = -1e30f, m1 = -1e30f, l0 = 0.f, l1 = 0.f;

    // K-tile prefetch helper (8 cp.async per thread)
    const float* kbase = qk + (size_t)bb * N_TOK * (2 * DIMM) + DIMM + h * DHEAD;
#define FILL_KT(KT, BUF)                                                      \
    {                                                                         \
        _Pragma("unroll")                                                     \
        for (int i = tid; i < 64 * 16; i += 128) {                            \
            int r = i >> 4, c = (i & 15) * 4;                                 \
            cp_async16(&Ks[BUF][r][c],                                        \
                       kbase + (size_t)((KT) * 64 + r) * (2 * DIMM) + c);     \
        }                                                                     \
        asm volatile("cp.async.commit_group;");                               \
    }

    FILL_KT(0, 0);

    for (int kt = 0; kt <= qt; kt++) {
        const int buf = kt & 1;
        if (kt + 1 <= qt) {
            FILL_KT(kt + 1, buf ^ 1);
            asm volatile("cp.async.wait_group 1;");
        } else {
            asm volatile("cp.async.wait_group 0;");
        }
        __syncthreads();

        // ---- S = Q @ K^T ----
        float sc[8][4];
#pragma unroll
        for (int nt = 0; nt < 8; nt++) {
            sc[nt][0] = sc[nt][1] = sc[nt][2] = sc[nt][3] = 0.f;
#pragma unroll
            for (int kc = 0; kc < 8; kc++) {
                unsigned b0 = __float_as_uint(Ks[buf][nt * 8 + g][kc * 8 + t]);
                unsigned b1 = __float_as_uint(Ks[buf][nt * 8 + g][kc * 8 + t + 4]);
                mma_tf32(sc[nt][0], sc[nt][1], sc[nt][2], sc[nt][3],
                         qf[kc][0], qf[kc][1], qf[kc][2], qf[kc][3], b0, b1);
            }
        }

        if (kt == qt) {
            const int r0 = w * 16 + g, r1 = r0 + 8;
#pragma unroll
            for (int nt = 0; nt < 8; nt++) {
                int col = nt * 8 + 2 * t;
                if (col     > r0) sc[nt][0] = -1e30f;
                if (col + 1 > r0) sc[nt][1] = -1e30f;
                if (col     > r1) sc[nt][2] = -1e30f;
                if (col + 1 > r1) sc[nt][3] = -1e30f;
            }
        }

        // ---- online softmax ----
        float tmax0 = -1e30f, tmax1 = -1e30f;
#pragma unroll
        for (int nt = 0; nt < 8; nt++) {
            tmax0 = fmaxf(tmax0, fmaxf(sc[nt][0], sc[nt][1]));
            tmax1 = fmaxf(tmax1, fmaxf(sc[nt][2], sc[nt][3]));
        }
        tmax0 = fmaxf(tmax0, __shfl_xor_sync(0xffffffffu, tmax0, 1));
        tmax0 = fmaxf(tmax0, __shfl_xor_sync(0xffffffffu, tmax0, 2));
        tmax1 = fmaxf(tmax1, __shfl_xor_sync(0xffffffffu, tmax1, 1));
        tmax1 = fmaxf(tmax1, __shfl_xor_sync(0xffffffffu, tmax1, 2));

        float mn0 = fmaxf(m0, tmax0), mn1 = fmaxf(m1, tmax1);
        float corr0 = __expf(m0 - mn0), corr1 = __expf(m1 - mn1);
        m0 = mn0; m1 = mn1;

        float ls0 = 0.f, ls1 = 0.f;
        unsigned pu[8][4];
#pragma unroll
        for (int nt = 0; nt < 8; nt++) {
            float p0 = __expf(sc[nt][0] - mn0);
            float p1 = __expf(sc[nt][1] - mn0);
            float p2 = __expf(sc[nt][2] - mn1);
            float p3 = __expf(sc[nt][3] - mn1);
            ls0 += p0 + p1;
            ls1 += p2 + p3;
            pu[nt][0] = f2tf32(p0);
            pu[nt][1] = f2tf32(p1);
            pu[nt][2] = f2tf32(p2);
            pu[nt][3] = f2tf32(p3);
        }
        ls0 += __shfl_xor_sync(0xffffffffu, ls0, 1);
        ls0 += __shfl_xor_sync(0xffffffffu, ls0, 2);
        ls1 += __shfl_xor_sync(0xffffffffu, ls1, 1);
        ls1 += __shfl_xor_sync(0xffffffffu, ls1, 2);
        l0 = l0 * corr0 + ls0;
        l1 = l1 * corr1 + ls1;

#pragma unroll
        for (int nt = 0; nt < 8; nt++) {
            o[nt][0] *= corr0; o[nt][1] *= corr0;
            o[nt][2] *= corr1; o[nt][3] *= corr1;
        }

        // ---- O += P @ V (V = K tile); P C-frag -> A-frag via shuffles ----
#pragma unroll
        for (int kc = 0; kc < 8; kc++) {
            int src0 = (lane & 28) | (t >> 1);
            int src1 = src0 + 2;
            unsigned v00 = __shfl_sync(0xffffffffu, pu[kc][0], src0);
            unsigned v01 = __shfl_sync(0xffffffffu, pu[kc][1], src0);
            unsigned v10 = __shfl_sync(0xffffffffu, pu[kc][2], src0);
            unsigned v11 = __shfl_sync(0xffffffffu, pu[kc][3], src0);
            unsigned v20 = __shfl_sync(0xffffffffu, pu[kc][0], src1);
            unsigned v21 = __shfl_sync(0xffffffffu, pu[kc][1], src1);
            unsigned v30 = __shfl_sync(0xffffffffu, pu[kc][2], src1);
            unsigned v31 = __shfl_sync(0xffffffffu, pu[kc][3], src1);
            bool odd = (t & 1);
            unsigned a0 = odd ? v01 : v00;
            unsigned a1 = odd ? v11 : v10;
            unsigned a2 = odd ? v21 : v20;
            unsigned a3 = odd ? v31 : v30;

#pragma unroll
            for (int nt = 0; nt < 8; nt++) {
                unsigned b0 = __float_as_uint(Ks[buf][kc * 8 + t][nt * 8 + g]);
                unsigned b1 = __float_as_uint(Ks[buf][kc * 8 + t + 4][nt * 8 + g]);
                mma_tf32(o[nt][0], o[nt][1], o[nt][2], o[nt][3],
                         a0, a1, a2, a3, b0, b1);
            }
        }
        __syncthreads();
    }

    // ---- epilogue: normalize, round to tf32 (feeds GEMM2), store ----
    const float inv0 = 1.f / l0, inv1 = 1.f / l1;
    float* op0 = out + (size_t)(qrow0 + g) * DIMM + h * DHEAD;
    float* op1 = op0 + (size_t)8 * DIMM;
#pragma unroll
    for (int nt = 0; nt < 8; nt++) {
        *(float2*)(op0 + nt * 8 + 2 * t) = make_float2(
            __uint_as_float(f2tf32(o[nt][0] * inv0)),
            __uint_as_float(f2tf32(o[nt][1] * inv0)));
        *(float2*)(op1 + nt * 8 + 2 * t) = make_float2(
            __uint_as_float(f2tf32(o[nt][2] * inv1)),
            __uint_as_float(f2tf32(o[nt][3] * inv1)));
    }
#undef FILL_KT
}

// ---------------------------------------------------------------------------
extern "C" void kernel_launch(void* const* d_in, const int* in_sizes, int n_in,
                              void* d_out, int out_size)
{
    const float* x     = (const float*)d_in[0];
    const float* W_qk  = (const float*)d_in[1];
    const float* W_out = (const float*)d_in[2];
    float* out = (float*)d_out;

    float *qkbuf, *aobuf, *xr, *wqkr, *wor;
    cudaGetSymbolAddress((void**)&qkbuf, g_qk);
    cudaGetSymbolAddress((void**)&aobuf, g_ao);
    cudaGetSymbolAddress((void**)&xr,    g_xr);
    cudaGetSymbolAddress((void**)&wqkr,  g_wqkr);
    cudaGetSymbolAddress((void**)&wor,   g_wor);

    const int nx  = NBATCH * N_TOK * DIMM / 4;       // x float4s
    const int nwq = DIMM * 2 * DIMM / 4;
    const int nwo = DIMM * DIMM / 4;
    round_kernel<<<(nx  + 255) / 256, 256>>>(x,     xr,   nx);
    round_kernel<<<(nwq + 255) / 256, 256>>>(W_qk,  wqkr, nwq);
    round_kernel<<<(nwo + 255) / 256, 256>>>(W_out, wor,  nwo);

    // qk = x @ W_qk (rounded output feeds attention)
    tgemm_kernel<true><<<dim3((2 * DIMM) / 128, (NBATCH * N_TOK) / 128), 256>>>(
        xr, wqkr, qkbuf, NBATCH * N_TOK, 2 * DIMM, DIMM);
    // causal attention (K reused as V); emits tf32-rounded output
    attn_tc_kernel<<<dim3(N_TOK / 64, NHEAD, NBATCH), 128>>>(qkbuf, aobuf);
    // out = ao @ W_out (final fp32 output, no rounding)
    tgemm_kernel<false><<<dim3(DIMM / 128, (NBATCH * N_TOK) / 128), 256>>>(
        aobuf, wor, out, NBATCH * N_TOK, DIMM, DIMM);
}

// round 7
// speedup vs baseline: 1.0456x; 1.0456x over previous
#include <cuda_runtime.h>
#include <cuda_bf16.h>
#include <math.h>

#define N_TOK  2048
#define DIMM   1024
#define NBATCH 2
#define NHEAD  16
#define DHEAD  64
#define BETA_V 0.125f

// Scratch (static device allocations — no cudaMalloc anywhere)
__device__ float g_qk[(size_t)(NBATCH * N_TOK) * (2 * DIMM)];  // 32 MB
__device__ float g_ao[(size_t)(NBATCH * N_TOK) * DIMM];        // 16 MB
__device__ float g_xr[(size_t)(NBATCH * N_TOK) * DIMM];        // 16 MB rounded x
__device__ float g_wqkr[(size_t)DIMM * (2 * DIMM)];            //  8 MB rounded W_qk
__device__ float g_wor[(size_t)DIMM * DIMM];                   //  4 MB rounded W_out

// ---------------------------------------------------------------------------
// helpers
// ---------------------------------------------------------------------------
__device__ __forceinline__ unsigned f2tf32(float x) {
    unsigned u;
    asm("cvt.rna.tf32.f32 %0, %1;" : "=r"(u) : "f"(x));
    return u;
}

__device__ __forceinline__ void mma_tf32(
    float& c0, float& c1, float& c2, float& c3,
    unsigned a0, unsigned a1, unsigned a2, unsigned a3,
    unsigned b0, unsigned b1)
{
    asm volatile(
        "mma.sync.aligned.m16n8k8.row.col.f32.tf32.tf32.f32 "
        "{%0,%1,%2,%3}, {%4,%5,%6,%7}, {%8,%9}, {%0,%1,%2,%3};"
        : "+f"(c0), "+f"(c1), "+f"(c2), "+f"(c3)
        : "r"(a0), "r"(a1), "r"(a2), "r"(a3), "r"(b0), "r"(b1));
}

__device__ __forceinline__ void cp_async16(void* smem, const void* gmem) {
    unsigned saddr = (unsigned)__cvta_generic_to_shared(smem);
    asm volatile("cp.async.cg.shared.global [%0], [%1], 16;"
                 :: "r"(saddr), "l"(gmem));
}

// ---------------------------------------------------------------------------
// Elementwise tf32 pre-round
// ---------------------------------------------------------------------------
__global__ void __launch_bounds__(256) round_kernel(
    const float* __restrict__ src, float* __restrict__ dst, int n4)
{
    int i = blockIdx.x * 256 + threadIdx.x;
    if (i < n4) {
        float4 v = ((const float4*)src)[i];
        float4 o;
        o.x = __uint_as_float(f2tf32(v.x));
        o.y = __uint_as_float(f2tf32(v.y));
        o.z = __uint_as_float(f2tf32(v.z));
        o.w = __uint_as_float(f2tf32(v.w));
        ((float4*)dst)[i] = o;
    }
}

// ---------------------------------------------------------------------------
// tf32 GEMM, inputs PRE-ROUNDED. 128x128 tile, BK=16, 3-stage cp.async.
// ---------------------------------------------------------------------------
#define AS_STR 20
#define BS_STR 136

template <bool ROUND_OUT>
__global__ void __launch_bounds__(256) tgemm_kernel(
    const float* __restrict__ A, const float* __restrict__ B,
    float* __restrict__ C, int M, int N, int K)
{
    __shared__ float As[3][128][AS_STR];
    __shared__ float Bs[3][16][BS_STR];

    const int tid  = threadIdx.x;
    const int w    = tid >> 5;
    const int lane = tid & 31;
    const int g    = lane >> 2;
    const int t    = lane & 3;
    const int wm   = (w & 3) * 32;
    const int wn   = (w >> 2) * 64;

    const int mbase = blockIdx.y * 128;
    const int nbase = blockIdx.x * 128;

    const int arow0 = tid >> 2,         acc0 = (tid & 3) * 4;
    const int arow1 = (tid + 256) >> 2, acc1 = ((tid + 256) & 3) * 4;
    const int brow0 = tid >> 5,         bcc0 = (tid & 31) * 4;
    const int brow1 = (tid + 256) >> 5, bcc1 = ((tid + 256) & 31) * 4;

    float acc[2][8][4];
#pragma unroll
    for (int mt = 0; mt < 2; mt++)
#pragma unroll
        for (int nt = 0; nt < 8; nt++)
#pragma unroll
            for (int j = 0; j < 4; j++) acc[mt][nt][j] = 0.f;

    const int NIT = K / 16;

#pragma unroll
    for (int s = 0; s < 2; s++) {
        const int k0 = s * 16;
        cp_async16(&As[s][arow0][acc0], A + (size_t)(mbase + arow0) * K + k0 + acc0);
        cp_async16(&As[s][arow1][acc1], A + (size_t)(mbase + arow1) * K + k0 + acc1);
        cp_async16(&Bs[s][brow0][bcc0], B + (size_t)(k0 + brow0) * N + nbase + bcc0);
        cp_async16(&Bs[s][brow1][bcc1], B + (size_t)(k0 + brow1) * N + nbase + bcc1);
        asm volatile("cp.async.commit_group;");
    }

    int buf = 0;
    for (int it = 0; it < NIT; it++) {
        if (it + 1 < NIT)
            asm volatile("cp.async.wait_group 1;");
        else
            asm volatile("cp.async.wait_group 0;");
        __syncthreads();

#pragma unroll
        for (int kc = 0; kc < 2; kc++) {
            unsigned af[2][4];
#pragma unroll
            for (int mt = 0; mt < 2; mt++) {
                const int m = wm + mt * 16;
                af[mt][0] = __float_as_uint(As[buf][m + g][kc * 8 + t]);
                af[mt][1] = __float_as_uint(As[buf][m + 8 + g][kc * 8 + t]);
                af[mt][2] = __float_as_uint(As[buf][m + g][kc * 8 + t + 4]);
                af[mt][3] = __float_as_uint(As[buf][m + 8 + g][kc * 8 + t + 4]);
            }
#pragma unroll
            for (int nt = 0; nt < 8; nt++) {
                unsigned b0 = __float_as_uint(Bs[buf][kc * 8 + t][wn + nt * 8 + g]);
                unsigned b1 = __float_as_uint(Bs[buf][kc * 8 + t + 4][wn + nt * 8 + g]);
                mma_tf32(acc[0][nt][0], acc[0][nt][1], acc[0][nt][2], acc[0][nt][3],
                         af[0][0], af[0][1], af[0][2], af[0][3], b0, b1);
                mma_tf32(acc[1][nt][0], acc[1][nt][1], acc[1][nt][2], acc[1][nt][3],
                         af[1][0], af[1][1], af[1][2], af[1][3], b0, b1);
            }
        }

        if (it + 2 < NIT) {
            const int k0 = (it + 2) * 16;
            const int nb = (it + 2) % 3;
            cp_async16(&As[nb][arow0][acc0], A + (size_t)(mbase + arow0) * K + k0 + acc0);
            cp_async16(&As[nb][arow1][acc1], A + (size_t)(mbase + arow1) * K + k0 + acc1);
            cp_async16(&Bs[nb][brow0][bcc0], B + (size_t)(k0 + brow0) * N + nbase + bcc0);
            cp_async16(&Bs[nb][brow1][bcc1], B + (size_t)(k0 + brow1) * N + nbase + bcc1);
            asm volatile("cp.async.commit_group;");
        }
        __syncthreads();
        buf = (buf + 1 == 3) ? 0 : buf + 1;
    }

#pragma unroll
    for (int mt = 0; mt < 2; mt++) {
        const int r0 = mbase + wm + mt * 16 + g;
#pragma unroll
        for (int nt = 0; nt < 8; nt++) {
            const int col = nbase + wn + nt * 8 + 2 * t;
            float v0 = acc[mt][nt][0], v1 = acc[mt][nt][1];
            float v2 = acc[mt][nt][2], v3 = acc[mt][nt][3];
            if (ROUND_OUT) {
                v0 = __uint_as_float(f2tf32(v0));
                v1 = __uint_as_float(f2tf32(v1));
                v2 = __uint_as_float(f2tf32(v2));
                v3 = __uint_as_float(f2tf32(v3));
            }
            *(float2*)(C + (size_t)r0 * N + col)       = make_float2(v0, v1);
            *(float2*)(C + (size_t)(r0 + 8) * N + col) = make_float2(v2, v3);
        }
    }
}

// ---------------------------------------------------------------------------
// Tensor-core causal flash attention v2.
// 256 threads (8 warps), 128 q-rows per block; warp w owns rows w*16..+15.
// K tile kept in TWO smem copies: Ks (stride 68, conflict-free S-stage) and
// Vs (stride 72, conflict-free PV-stage). Double-buffered cp.async.
// Per-warp causal bound: warp computes only kt <= 2*qt + (w>>2).
// ---------------------------------------------------------------------------
#define KS_STR 68
#define VS_STR 72
#define KS_ELEMS (2 * 64 * KS_STR)                 // 8704 floats
#define ATTN_SMEM_BYTES ((KS_ELEMS + 2 * 64 * VS_STR) * 4)  // 71680 B

__global__ void __launch_bounds__(256) attn_tc_kernel(
    const float* __restrict__ qk, float* __restrict__ out)
{
    extern __shared__ float sm[];
    float* Ks = sm;               // [2][64][KS_STR]
    float* Vs = sm + KS_ELEMS;    // [2][64][VS_STR]

    const int qt = blockIdx.x, h = blockIdx.y, bb = blockIdx.z;
    const int tid  = threadIdx.x;
    const int w    = tid >> 5;
    const int lane = tid & 31;
    const int g    = lane >> 2;
    const int t    = lane & 3;

    const int qrow0 = bb * N_TOK + qt * 128 + w * 16;
    // qk pre-rounded tf32; *2^-3 exact -> no cvt needed.
    unsigned qf[8][4];
#pragma unroll
    for (int kc = 0; kc < 8; kc++) {
        const float* qp  = qk + (size_t)(qrow0 + g) * (2 * DIMM) + h * DHEAD + kc * 8;
        const float* qp8 = qp + (size_t)8 * (2 * DIMM);
        qf[kc][0] = __float_as_uint(qp[t]      * BETA_V);
        qf[kc][1] = __float_as_uint(qp8[t]     * BETA_V);
        qf[kc][2] = __float_as_uint(qp[t + 4]  * BETA_V);
        qf[kc][3] = __float_as_uint(qp8[t + 4] * BETA_V);
    }

    float o[8][4];
#pragma unroll
    for (int nt = 0; nt < 8; nt++)
#pragma unroll
        for (int j = 0; j < 4; j++) o[nt][j] = 0.f;
    float m0 = -1e30f, m1 = -1e30f, l0 = 0.f, l1 = 0.f;

    const int ktmax = 2 * qt + 1;           // last key tile for this block
    const int diagw = 2 * qt + (w >> 2);    // this warp's diagonal tile

    const float* kbase = qk + (size_t)bb * N_TOK * (2 * DIMM) + DIMM + h * DHEAD;
#define FILL_KT(KT, BUF)                                                       \
    {                                                                          \
        _Pragma("unroll")                                                      \
        for (int i = tid; i < 64 * 16; i += 256) {                             \
            int r = i >> 4, c = (i & 15) * 4;                                  \
            const float* src = kbase + (size_t)((KT) * 64 + r) * (2 * DIMM) + c; \
            cp_async16(&Ks[((BUF) * 64 + r) * KS_STR + c], src);               \
            cp_async16(&Vs[((BUF) * 64 + r) * VS_STR + c], src);               \
        }                                                                      \
        asm volatile("cp.async.commit_group;");                                \
    }

    FILL_KT(0, 0);

    for (int kt = 0; kt <= ktmax; kt++) {
        const int buf = kt & 1;
        if (kt + 1 <= ktmax) {
            FILL_KT(kt + 1, buf ^ 1);
            asm volatile("cp.async.wait_group 1;");
        } else {
            asm volatile("cp.async.wait_group 0;");
        }
        __syncthreads();

        if (kt <= diagw) {
            // ---- S = Q @ K^T ----
            const float* KsB = Ks + buf * 64 * KS_STR;
            float sc[8][4];
#pragma unroll
            for (int nt = 0; nt < 8; nt++) {
                sc[nt][0] = sc[nt][1] = sc[nt][2] = sc[nt][3] = 0.f;
#pragma unroll
                for (int kc = 0; kc < 8; kc++) {
                    unsigned b0 = __float_as_uint(KsB[(nt * 8 + g) * KS_STR + kc * 8 + t]);
                    unsigned b1 = __float_as_uint(KsB[(nt * 8 + g) * KS_STR + kc * 8 + t + 4]);
                    mma_tf32(sc[nt][0], sc[nt][1], sc[nt][2], sc[nt][3],
                             qf[kc][0], qf[kc][1], qf[kc][2], qf[kc][3], b0, b1);
                }
            }

            // ---- causal mask (warp's diagonal tile only) ----
            if (kt == diagw) {
                const int lr0 = w * 16 + g, lr1 = lr0 + 8;
                const int cb  = (w >> 2) * 64;
#pragma unroll
                for (int nt = 0; nt < 8; nt++) {
                    int col = cb + nt * 8 + 2 * t;
                    if (col     > lr0) sc[nt][0] = -1e30f;
                    if (col + 1 > lr0) sc[nt][1] = -1e30f;
                    if (col     > lr1) sc[nt][2] = -1e30f;
                    if (col + 1 > lr1) sc[nt][3] = -1e30f;
                }
            }

            // ---- online softmax ----
            float tmax0 = -1e30f, tmax1 = -1e30f;
#pragma unroll
            for (int nt = 0; nt < 8; nt++) {
                tmax0 = fmaxf(tmax0, fmaxf(sc[nt][0], sc[nt][1]));
                tmax1 = fmaxf(tmax1, fmaxf(sc[nt][2], sc[nt][3]));
            }
            tmax0 = fmaxf(tmax0, __shfl_xor_sync(0xffffffffu, tmax0, 1));
            tmax0 = fmaxf(tmax0, __shfl_xor_sync(0xffffffffu, tmax0, 2));
            tmax1 = fmaxf(tmax1, __shfl_xor_sync(0xffffffffu, tmax1, 1));
            tmax1 = fmaxf(tmax1, __shfl_xor_sync(0xffffffffu, tmax1, 2));

            float mn0 = fmaxf(m0, tmax0), mn1 = fmaxf(m1, tmax1);
            float corr0 = __expf(m0 - mn0), corr1 = __expf(m1 - mn1);
            m0 = mn0; m1 = mn1;

            float ls0 = 0.f, ls1 = 0.f;
            unsigned pu[8][4];
#pragma unroll
            for (int nt = 0; nt < 8; nt++) {
                float p0 = __expf(sc[nt][0] - mn0);
                float p1 = __expf(sc[nt][1] - mn0);
                float p2 = __expf(sc[nt][2] - mn1);
                float p3 = __expf(sc[nt][3] - mn1);
                ls0 += p0 + p1;
                ls1 += p2 + p3;
                pu[nt][0] = f2tf32(p0);
                pu[nt][1] = f2tf32(p1);
                pu[nt][2] = f2tf32(p2);
                pu[nt][3] = f2tf32(p3);
            }
            ls0 += __shfl_xor_sync(0xffffffffu, ls0, 1);
            ls0 += __shfl_xor_sync(0xffffffffu, ls0, 2);
            ls1 += __shfl_xor_sync(0xffffffffu, ls1, 1);
            ls1 += __shfl_xor_sync(0xffffffffu, ls1, 2);
            l0 = l0 * corr0 + ls0;
            l1 = l1 * corr1 + ls1;

#pragma unroll
            for (int nt = 0; nt < 8; nt++) {
                o[nt][0] *= corr0; o[nt][1] *= corr0;
                o[nt][2] *= corr1; o[nt][3] *= corr1;
            }

            // ---- O += P @ V (Vs copy: conflict-free banks) ----
            const float* VsB = Vs + buf * 64 * VS_STR;
#pragma unroll
            for (int kc = 0; kc < 8; kc++) {
                int src0 = (lane & 28) | (t >> 1);
                int src1 = src0 + 2;
                unsigned v00 = __shfl_sync(0xffffffffu, pu[kc][0], src0);
                unsigned v01 = __shfl_sync(0xffffffffu, pu[kc][1], src0);
                unsigned v10 = __shfl_sync(0xffffffffu, pu[kc][2], src0);
                unsigned v11 = __shfl_sync(0xffffffffu, pu[kc][3], src0);
                unsigned v20 = __shfl_sync(0xffffffffu, pu[kc][0], src1);
                unsigned v21 = __shfl_sync(0xffffffffu, pu[kc][1], src1);
                unsigned v30 = __shfl_sync(0xffffffffu, pu[kc][2], src1);
                unsigned v31 = __shfl_sync(0xffffffffu, pu[kc][3], src1);
                bool odd = (t & 1);
                unsigned a0 = odd ? v01 : v00;
                unsigned a1 = odd ? v11 : v10;
                unsigned a2 = odd ? v21 : v20;
                unsigned a3 = odd ? v31 : v30;

#pragma unroll
                for (int nt = 0; nt < 8; nt++) {
                    unsigned b0 = __float_as_uint(VsB[(kc * 8 + t) * VS_STR + nt * 8 + g]);
                    unsigned b1 = __float_as_uint(VsB[(kc * 8 + t + 4) * VS_STR + nt * 8 + g]);
                    mma_tf32(o[nt][0], o[nt][1], o[nt][2], o[nt][3],
                             a0, a1, a2, a3, b0, b1);
                }
            }
        }
        __syncthreads();
    }

    // ---- epilogue: normalize, round to tf32 (feeds GEMM2), store ----
    const float inv0 = 1.f / l0, inv1 = 1.f / l1;
    float* op0 = out + (size_t)(qrow0 + g) * DIMM + h * DHEAD;
    float* op1 = op0 + (size_t)8 * DIMM;
#pragma unroll
    for (int nt = 0; nt < 8; nt++) {
        *(float2*)(op0 + nt * 8 + 2 * t) = make_float2(
            __uint_as_float(f2tf32(o[nt][0] * inv0)),
            __uint_as_float(f2tf32(o[nt][1] * inv0)));
        *(float2*)(op1 + nt * 8 + 2 * t) = make_float2(
            __uint_as_float(f2tf32(o[nt][2] * inv1)),
            __uint_as_float(f2tf32(o[nt][3] * inv1)));
    }
#undef FILL_KT
}

// ---------------------------------------------------------------------------
extern "C" void kernel_launch(void* const* d_in, const int* in_sizes, int n_in,
                              void* d_out, int out_size)
{
    const float* x     = (const float*)d_in[0];
    const float* W_qk  = (const float*)d_in[1];
    const float* W_out = (const float*)d_in[2];
    float* out = (float*)d_out;

    float *qkbuf, *aobuf, *xr, *wqkr, *wor;
    cudaGetSymbolAddress((void**)&qkbuf, g_qk);
    cudaGetSymbolAddress((void**)&aobuf, g_ao);
    cudaGetSymbolAddress((void**)&xr,    g_xr);
    cudaGetSymbolAddress((void**)&wqkr,  g_wqkr);
    cudaGetSymbolAddress((void**)&wor,   g_wor);

    static bool attr_set = false;
    if (!attr_set) {
        cudaFuncSetAttribute(attn_tc_kernel,
                             cudaFuncAttributeMaxDynamicSharedMemorySize,
                             ATTN_SMEM_BYTES);
        attr_set = true;
    }

    const int nx  = NBATCH * N_TOK * DIMM / 4;
    const int nwq = DIMM * 2 * DIMM / 4;
    const int nwo = DIMM * DIMM / 4;
    round_kernel<<<(nx  + 255) / 256, 256>>>(x,     xr,   nx);
    round_kernel<<<(nwq + 255) / 256, 256>>>(W_qk,  wqkr, nwq);
    round_kernel<<<(nwo + 255) / 256, 256>>>(W_out, wor,  nwo);

    // qk = x @ W_qk (tf32-rounded output feeds attention)
    tgemm_kernel<true><<<dim3((2 * DIMM) / 128, (NBATCH * N_TOK) / 128), 256>>>(
        xr, wqkr, qkbuf, NBATCH * N_TOK, 2 * DIMM, DIMM);
    // causal attention (K reused as V)
    attn_tc_kernel<<<dim3(N_TOK / 128, NHEAD, NBATCH), 256, ATTN_SMEM_BYTES>>>(
        qkbuf, aobuf);
    // out = ao @ W_out
    tgemm_kernel<false><<<dim3(DIMM / 128, (NBATCH * N_TOK) / 128), 256>>>(
        aobuf, wor, out, NBATCH * N_TOK, DIMM, DIMM);
}

// round 8
// speedup vs baseline: 1.0794x; 1.0323x over previous
#include <cuda_runtime.h>
#include <cuda_bf16.h>
#include <math.h>

#define N_TOK  2048
#define DIMM   1024
#define NBATCH 2
#define NHEAD  16
#define DHEAD  64
#define BETA_V 0.125f

// Scratch (static device allocations — no cudaMalloc anywhere)
__device__ float g_qk[(size_t)(NBATCH * N_TOK) * (2 * DIMM)];  // 32 MB
__device__ float g_ao[(size_t)(NBATCH * N_TOK) * DIMM];        // 16 MB
__device__ float g_xr[(size_t)(NBATCH * N_TOK) * DIMM];        // 16 MB rounded x
__device__ float g_wqkr[(size_t)DIMM * (2 * DIMM)];            //  8 MB rounded W_qk
__device__ float g_wor[(size_t)DIMM * DIMM];                   //  4 MB rounded W_out

// ---------------------------------------------------------------------------
// helpers
// ---------------------------------------------------------------------------
__device__ __forceinline__ unsigned f2tf32(float x) {
    unsigned u;
    asm("cvt.rna.tf32.f32 %0, %1;" : "=r"(u) : "f"(x));
    return u;
}

__device__ __forceinline__ void mma_tf32(
    float& c0, float& c1, float& c2, float& c3,
    unsigned a0, unsigned a1, unsigned a2, unsigned a3,
    unsigned b0, unsigned b1)
{
    asm volatile(
        "mma.sync.aligned.m16n8k8.row.col.f32.tf32.tf32.f32 "
        "{%0,%1,%2,%3}, {%4,%5,%6,%7}, {%8,%9}, {%0,%1,%2,%3};"
        : "+f"(c0), "+f"(c1), "+f"(c2), "+f"(c3)
        : "r"(a0), "r"(a1), "r"(a2), "r"(a3), "r"(b0), "r"(b1));
}

__device__ __forceinline__ void cp_async16(void* smem, const void* gmem) {
    unsigned saddr = (unsigned)__cvta_generic_to_shared(smem);
    asm volatile("cp.async.cg.shared.global [%0], [%1], 16;"
                 :: "r"(saddr), "l"(gmem));
}

// ldmatrix x4 on 32-bit (tf32) data: each 8x8 "b16 matrix" row = 16B = 4 tf32.
// Lane L supplies the address of row (L&7) of matrix (L>>3).
// Result: reg j, lane L = element (row L/4, col L%4) of tf32-matrix j.
__device__ __forceinline__ void ldsm_x4(
    unsigned& r0, unsigned& r1, unsigned& r2, unsigned& r3, const void* p)
{
    unsigned a = (unsigned)__cvta_generic_to_shared(p);
    asm volatile("ldmatrix.sync.aligned.m8n8.x4.shared.b16 {%0,%1,%2,%3}, [%4];"
                 : "=r"(r0), "=r"(r1), "=r"(r2), "=r"(r3) : "r"(a));
}

// ---------------------------------------------------------------------------
// Fused elementwise tf32 pre-round of x, W_qk, W_out (one launch)
// ---------------------------------------------------------------------------
__global__ void __launch_bounds__(256) round3_kernel(
    const float* __restrict__ s0, float* __restrict__ d0, int n0,
    const float* __restrict__ s1, float* __restrict__ d1, int n1,
    const float* __restrict__ s2, float* __restrict__ d2, int n2)
{
    int i = blockIdx.x * 256 + threadIdx.x;
    const float* s; float* d; int j = i;
    if (j < n0)                { s = s0; d = d0; }
    else if ((j -= n0) < n1)   { s = s1; d = d1; }
    else if ((j -= n1) < n2)   { s = s2; d = d2; }
    else return;
    float4 v = ((const float4*)s)[j];
    float4 o;
    o.x = __uint_as_float(f2tf32(v.x));
    o.y = __uint_as_float(f2tf32(v.y));
    o.z = __uint_as_float(f2tf32(v.z));
    o.w = __uint_as_float(f2tf32(v.w));
    ((float4*)d)[j] = o;
}

// ---------------------------------------------------------------------------
// tf32 GEMM, inputs PRE-ROUNDED. 128x128 tile, BK=16, 3-stage cp.async.
// A-fragments via ldmatrix.x4 (As rows are [m][k] -> native orientation).
// ---------------------------------------------------------------------------
#define AS_STR 20
#define BS_STR 136

template <bool ROUND_OUT>
__global__ void __launch_bounds__(256) tgemm_kernel(
    const float* __restrict__ A, const float* __restrict__ B,
    float* __restrict__ C, int M, int N, int K)
{
    __shared__ float As[3][128][AS_STR];
    __shared__ float Bs[3][16][BS_STR];

    const int tid  = threadIdx.x;
    const int w    = tid >> 5;
    const int lane = tid & 31;
    const int g    = lane >> 2;
    const int t    = lane & 3;
    const int wm   = (w & 3) * 32;
    const int wn   = (w >> 2) * 64;

    const int mbase = blockIdx.y * 128;
    const int nbase = blockIdx.x * 128;

    const int arow0 = tid >> 2,         acc0 = (tid & 3) * 4;
    const int arow1 = (tid + 256) >> 2, acc1 = ((tid + 256) & 3) * 4;
    const int brow0 = tid >> 5,         bcc0 = (tid & 31) * 4;
    const int brow1 = (tid + 256) >> 5, bcc1 = ((tid + 256) & 31) * 4;

    // ldmatrix lane mapping for A-frags: row (lane&7), matrix (lane>>3).
    // matrix 0: rows m..m+7  k 0-3 | 1: m+8..15 k 0-3 | 2: m..m+7 k 4-7 | 3: m+8..15 k 4-7
    const int lrow = (lane & 7) + ((lane >> 3) & 1) * 8;  // row-in-16 block
    const int lcol = (lane >> 4) * 4;                     // k offset 0 or 4

    float acc[2][8][4];
#pragma unroll
    for (int mt = 0; mt < 2; mt++)
#pragma unroll
        for (int nt = 0; nt < 8; nt++)
#pragma unroll
            for (int j = 0; j < 4; j++) acc[mt][nt][j] = 0.f;

    const int NIT = K / 16;

#pragma unroll
    for (int s = 0; s < 2; s++) {
        const int k0 = s * 16;
        cp_async16(&As[s][arow0][acc0], A + (size_t)(mbase + arow0) * K + k0 + acc0);
        cp_async16(&As[s][arow1][acc1], A + (size_t)(mbase + arow1) * K + k0 + acc1);
        cp_async16(&Bs[s][brow0][bcc0], B + (size_t)(k0 + brow0) * N + nbase + bcc0);
        cp_async16(&Bs[s][brow1][bcc1], B + (size_t)(k0 + brow1) * N + nbase + bcc1);
        asm volatile("cp.async.commit_group;");
    }

    int buf = 0;
    for (int it = 0; it < NIT; it++) {
        if (it + 1 < NIT)
            asm volatile("cp.async.wait_group 1;");
        else
            asm volatile("cp.async.wait_group 0;");
        __syncthreads();

        // A-frags for both kc and both mt via 4 ldmatrix.x4
        unsigned af[2][2][4];   // [kc][mt][reg]
#pragma unroll
        for (int kc = 0; kc < 2; kc++)
#pragma unroll
            for (int mt = 0; mt < 2; mt++)
                ldsm_x4(af[kc][mt][0], af[kc][mt][1], af[kc][mt][2], af[kc][mt][3],
                        &As[buf][wm + mt * 16 + lrow][kc * 8 + lcol]);

#pragma unroll
        for (int kc = 0; kc < 2; kc++) {
#pragma unroll
            for (int nt = 0; nt < 8; nt++) {
                unsigned b0 = __float_as_uint(Bs[buf][kc * 8 + t][wn + nt * 8 + g]);
                unsigned b1 = __float_as_uint(Bs[buf][kc * 8 + t + 4][wn + nt * 8 + g]);
                mma_tf32(acc[0][nt][0], acc[0][nt][1], acc[0][nt][2], acc[0][nt][3],
                         af[kc][0][0], af[kc][0][1], af[kc][0][2], af[kc][0][3], b0, b1);
                mma_tf32(acc[1][nt][0], acc[1][nt][1], acc[1][nt][2], acc[1][nt][3],
                         af[kc][1][0], af[kc][1][1], af[kc][1][2], af[kc][1][3], b0, b1);
            }
        }

        if (it + 2 < NIT) {
            const int k0 = (it + 2) * 16;
            const int nb = (it + 2) % 3;
            cp_async16(&As[nb][arow0][acc0], A + (size_t)(mbase + arow0) * K + k0 + acc0);
            cp_async16(&As[nb][arow1][acc1], A + (size_t)(mbase + arow1) * K + k0 + acc1);
            cp_async16(&Bs[nb][brow0][bcc0], B + (size_t)(k0 + brow0) * N + nbase + bcc0);
            cp_async16(&Bs[nb][brow1][bcc1], B + (size_t)(k0 + brow1) * N + nbase + bcc1);
            asm volatile("cp.async.commit_group;");
        }
        __syncthreads();
        buf = (buf + 1 == 3) ? 0 : buf + 1;
    }

#pragma unroll
    for (int mt = 0; mt < 2; mt++) {
        const int r0 = mbase + wm + mt * 16 + g;
#pragma unroll
        for (int nt = 0; nt < 8; nt++) {
            const int col = nbase + wn + nt * 8 + 2 * t;
            float v0 = acc[mt][nt][0], v1 = acc[mt][nt][1];
            float v2 = acc[mt][nt][2], v3 = acc[mt][nt][3];
            if (ROUND_OUT) {
                v0 = __uint_as_float(f2tf32(v0));
                v1 = __uint_as_float(f2tf32(v1));
                v2 = __uint_as_float(f2tf32(v2));
                v3 = __uint_as_float(f2tf32(v3));
            }
            *(float2*)(C + (size_t)r0 * N + col)       = make_float2(v0, v1);
            *(float2*)(C + (size_t)(r0 + 8) * N + col) = make_float2(v2, v3);
        }
    }
}

// ---------------------------------------------------------------------------
// Tensor-core causal flash attention v3.
// 256 threads (8 warps), 128 q-rows/block, warp w owns rows w*16..+15.
// S-stage K fragments via ldmatrix.x4 (Ks rows = [key][d], native).
// PV-stage scalar LDS from Vs (stride 72, conflict-free).
// Per-warp causal bound: warp computes only kt <= 2*qt + (w>>2).
// ---------------------------------------------------------------------------
#define KS_STR 68
#define VS_STR 72
#define KS_ELEMS (2 * 64 * KS_STR)
#define ATTN_SMEM_BYTES ((KS_ELEMS + 2 * 64 * VS_STR) * 4)  // 71680 B

__global__ void __launch_bounds__(256) attn_tc_kernel(
    const float* __restrict__ qk, float* __restrict__ out)
{
    extern __shared__ float sm[];
    float* Ks = sm;
    float* Vs = sm + KS_ELEMS;

    const int qt = blockIdx.x, h = blockIdx.y, bb = blockIdx.z;
    const int tid  = threadIdx.x;
    const int w    = tid >> 5;
    const int lane = tid & 31;
    const int g    = lane >> 2;
    const int t    = lane & 3;

    // ldmatrix lane mapping for S-stage B-frags:
    // LDSM #q covers kc = {2q, 2q+1}; matrix j = lane>>3:
    //   key = nt*8 + (lane&7),  d = 16*q + j*4
    const int ld_key = lane & 7;
    const int ld_d   = (lane >> 3) * 4;

    const int qrow0 = bb * N_TOK + qt * 128 + w * 16;
    unsigned qf[8][4];
#pragma unroll
    for (int kc = 0; kc < 8; kc++) {
        const float* qp  = qk + (size_t)(qrow0 + g) * (2 * DIMM) + h * DHEAD + kc * 8;
        const float* qp8 = qp + (size_t)8 * (2 * DIMM);
        qf[kc][0] = __float_as_uint(qp[t]      * BETA_V);
        qf[kc][1] = __float_as_uint(qp8[t]     * BETA_V);
        qf[kc][2] = __float_as_uint(qp[t + 4]  * BETA_V);
        qf[kc][3] = __float_as_uint(qp8[t + 4] * BETA_V);
    }

    float o[8][4];
#pragma unroll
    for (int nt = 0; nt < 8; nt++)
#pragma unroll
        for (int j = 0; j < 4; j++) o[nt][j] = 0.f;
    float m0 = -1e30f, m1 = -1e30f, l0 = 0.f, l1 = 0.f;

    const int ktmax = 2 * qt + 1;
    const int diagw = 2 * qt + (w >> 2);

    const float* kbase = qk + (size_t)bb * N_TOK * (2 * DIMM) + DIMM + h * DHEAD;
#define FILL_KT(KT, BUF)                                                       \
    {                                                                          \
        _Pragma("unroll")                                                      \
        for (int i = tid; i < 64 * 16; i += 256) {                             \
            int r = i >> 4, c = (i & 15) * 4;                                  \
            const float* src = kbase + (size_t)((KT) * 64 + r) * (2 * DIMM) + c; \
            cp_async16(&Ks[((BUF) * 64 + r) * KS_STR + c], src);               \
            cp_async16(&Vs[((BUF) * 64 + r) * VS_STR + c], src);               \
        }                                                                      \
        asm volatile("cp.async.commit_group;");                                \
    }

    FILL_KT(0, 0);

    for (int kt = 0; kt <= ktmax; kt++) {
        const int buf = kt & 1;
        if (kt + 1 <= ktmax) {
            FILL_KT(kt + 1, buf ^ 1);
            asm volatile("cp.async.wait_group 1;");
        } else {
            asm volatile("cp.async.wait_group 0;");
        }
        __syncthreads();

        if (kt <= diagw) {
            // ---- S = Q @ K^T  (B-frags via ldmatrix.x4) ----
            const float* KsB = Ks + buf * 64 * KS_STR;
            const float* ldb = KsB + ld_key * KS_STR + ld_d;
            float sc[8][4];
#pragma unroll
            for (int nt = 0; nt < 8; nt++) {
                sc[nt][0] = sc[nt][1] = sc[nt][2] = sc[nt][3] = 0.f;
#pragma unroll
                for (int q = 0; q < 4; q++) {
                    unsigned b0, b1, b2, b3;
                    ldsm_x4(b0, b1, b2, b3, ldb + nt * 8 * KS_STR + 16 * q);
                    mma_tf32(sc[nt][0], sc[nt][1], sc[nt][2], sc[nt][3],
                             qf[2 * q][0], qf[2 * q][1], qf[2 * q][2], qf[2 * q][3],
                             b0, b1);
                    mma_tf32(sc[nt][0], sc[nt][1], sc[nt][2], sc[nt][3],
                             qf[2 * q + 1][0], qf[2 * q + 1][1], qf[2 * q + 1][2], qf[2 * q + 1][3],
                             b2, b3);
                }
            }

            // ---- causal mask (warp's diagonal tile only) ----
            if (kt == diagw) {
                const int lr0 = w * 16 + g, lr1 = lr0 + 8;
                const int cb  = (w >> 2) * 64;
#pragma unroll
                for (int nt = 0; nt < 8; nt++) {
                    int col = cb + nt * 8 + 2 * t;
                    if (col     > lr0) sc[nt][0] = -1e30f;
                    if (col + 1 > lr0) sc[nt][1] = -1e30f;
                    if (col     > lr1) sc[nt][2] = -1e30f;
                    if (col + 1 > lr1) sc[nt][3] = -1e30f;
                }
            }

            // ---- online softmax ----
            float tmax0 = -1e30f, tmax1 = -1e30f;
#pragma unroll
            for (int nt = 0; nt < 8; nt++) {
                tmax0 = fmaxf(tmax0, fmaxf(sc[nt][0], sc[nt][1]));
                tmax1 = fmaxf(tmax1, fmaxf(sc[nt][2], sc[nt][3]));
            }
            tmax0 = fmaxf(tmax0, __shfl_xor_sync(0xffffffffu, tmax0, 1));
            tmax0 = fmaxf(tmax0, __shfl_xor_sync(0xffffffffu, tmax0, 2));
            tmax1 = fmaxf(tmax1, __shfl_xor_sync(0xffffffffu, tmax1, 1));
            tmax1 = fmaxf(tmax1, __shfl_xor_sync(0xffffffffu, tmax1, 2));

            float mn0 = fmaxf(m0, tmax0), mn1 = fmaxf(m1, tmax1);
            float corr0 = __expf(m0 - mn0), corr1 = __expf(m1 - mn1);
            m0 = mn0; m1 = mn1;

            float ls0 = 0.f, ls1 = 0.f;
            unsigned pu[8][4];
#pragma unroll
            for (int nt = 0; nt < 8; nt++) {
                float p0 = __expf(sc[nt][0] - mn0);
                float p1 = __expf(sc[nt][1] - mn0);
                float p2 = __expf(sc[nt][2] - mn1);
                float p3 = __expf(sc[nt][3] - mn1);
                ls0 += p0 + p1;
                ls1 += p2 + p3;
                pu[nt][0] = f2tf32(p0);
                pu[nt][1] = f2tf32(p1);
                pu[nt][2] = f2tf32(p2);
                pu[nt][3] = f2tf32(p3);
            }
            ls0 += __shfl_xor_sync(0xffffffffu, ls0, 1);
            ls0 += __shfl_xor_sync(0xffffffffu, ls0, 2);
            ls1 += __shfl_xor_sync(0xffffffffu, ls1, 1);
            ls1 += __shfl_xor_sync(0xffffffffu, ls1, 2);
            l0 = l0 * corr0 + ls0;
            l1 = l1 * corr1 + ls1;

#pragma unroll
            for (int nt = 0; nt < 8; nt++) {
                o[nt][0] *= corr0; o[nt][1] *= corr0;
                o[nt][2] *= corr1; o[nt][3] *= corr1;
            }

            // ---- O += P @ V (Vs copy: conflict-free scalar LDS) ----
            const float* VsB = Vs + buf * 64 * VS_STR;
#pragma unroll
            for (int kc = 0; kc < 8; kc++) {
                int src0 = (lane & 28) | (t >> 1);
                int src1 = src0 + 2;
                unsigned v00 = __shfl_sync(0xffffffffu, pu[kc][0], src0);
                unsigned v01 = __shfl_sync(0xffffffffu, pu[kc][1], src0);
                unsigned v10 = __shfl_sync(0xffffffffu, pu[kc][2], src0);
                unsigned v11 = __shfl_sync(0xffffffffu, pu[kc][3], src0);
                unsigned v20 = __shfl_sync(0xffffffffu, pu[kc][0], src1);
                unsigned v21 = __shfl_sync(0xffffffffu, pu[kc][1], src1);
                unsigned v30 = __shfl_sync(0xffffffffu, pu[kc][2], src1);
                unsigned v31 = __shfl_sync(0xffffffffu, pu[kc][3], src1);
                bool odd = (t & 1);
                unsigned a0 = odd ? v01 : v00;
                unsigned a1 = odd ? v11 : v10;
                unsigned a2 = odd ? v21 : v20;
                unsigned a3 = odd ? v31 : v30;

#pragma unroll
                for (int nt = 0; nt < 8; nt++) {
                    unsigned b0 = __float_as_uint(VsB[(kc * 8 + t) * VS_STR + nt * 8 + g]);
                    unsigned b1 = __float_as_uint(VsB[(kc * 8 + t + 4) * VS_STR + nt * 8 + g]);
                    mma_tf32(o[nt][0], o[nt][1], o[nt][2], o[nt][3],
                             a0, a1, a2, a3, b0, b1);
                }
            }
        }
        __syncthreads();
    }

    // ---- epilogue ----
    const float inv0 = 1.f / l0, inv1 = 1.f / l1;
    float* op0 = out + (size_t)(qrow0 + g) * DIMM + h * DHEAD;
    float* op1 = op0 + (size_t)8 * DIMM;
#pragma unroll
    for (int nt = 0; nt < 8; nt++) {
        *(float2*)(op0 + nt * 8 + 2 * t) = make_float2(
            __uint_as_float(f2tf32(o[nt][0] * inv0)),
            __uint_as_float(f2tf32(o[nt][1] * inv0)));
        *(float2*)(op1 + nt * 8 + 2 * t) = make_float2(
            __uint_as_float(f2tf32(o[nt][2] * inv1)),
            __uint_as_float(f2tf32(o[nt][3] * inv1)));
    }
#undef FILL_KT
}

// ---------------------------------------------------------------------------
extern "C" void kernel_launch(void* const* d_in, const int* in_sizes, int n_in,
                              void* d_out, int out_size)
{
    const float* x     = (const float*)d_in[0];
    const float* W_qk  = (const float*)d_in[1];
    const float* W_out = (const float*)d_in[2];
    float* out = (float*)d_out;

    float *qkbuf, *aobuf, *xr, *wqkr, *wor;
    cudaGetSymbolAddress((void**)&qkbuf, g_qk);
    cudaGetSymbolAddress((void**)&aobuf, g_ao);
    cudaGetSymbolAddress((void**)&xr,    g_xr);
    cudaGetSymbolAddress((void**)&wqkr,  g_wqkr);
    cudaGetSymbolAddress((void**)&wor,   g_wor);

    static bool attr_set = false;
    if (!attr_set) {
        cudaFuncSetAttribute(attn_tc_kernel,
                             cudaFuncAttributeMaxDynamicSharedMemorySize,
                             ATTN_SMEM_BYTES);
        attr_set = true;
    }

    const int nx  = NBATCH * N_TOK * DIMM / 4;
    const int nwq = DIMM * 2 * DIMM / 4;
    const int nwo = DIMM * DIMM / 4;
    const int ntot = nx + nwq + nwo;
    round3_kernel<<<(ntot + 255) / 256, 256>>>(x, xr, nx, W_qk, wqkr, nwq,
                                               W_out, wor, nwo);

    // qk = x @ W_qk (tf32-rounded output feeds attention)
    tgemm_kernel<true><<<dim3((2 * DIMM) / 128, (NBATCH * N_TOK) / 128), 256>>>(
        xr, wqkr, qkbuf, NBATCH * N_TOK, 2 * DIMM, DIMM);
    // causal attention (K reused as V)
    attn_tc_kernel<<<dim3(N_TOK / 128, NHEAD, NBATCH), 256, ATTN_SMEM_BYTES>>>(
        qkbuf, aobuf);
    // out = ao @ W_out
    tgemm_kernel<false><<<dim3(DIMM / 128, (NBATCH * N_TOK) / 128), 256>>>(
        aobuf, wor, out, NBATCH * N_TOK, DIMM, DIMM);
}

// round 10
// speedup vs baseline: 1.1158x; 1.0337x over previous
#include <cuda_runtime.h>
#include <cuda_bf16.h>
#include <math.h>

#define N_TOK  2048
#define DIMM   1024
#define NBATCH 2
#define NHEAD  16
#define DHEAD  64
#define BETA_V 0.125f
#define NQT    (N_TOK / 128)   // 16 q-tiles of 128 rows

// Scratch (static device allocations — no cudaMalloc anywhere)
__device__ float g_qk[(size_t)(NBATCH * N_TOK) * (2 * DIMM)];
__device__ float g_ao[(size_t)(NBATCH * N_TOK) * DIMM];
__device__ float g_xr[(size_t)(NBATCH * N_TOK) * DIMM];
__device__ float g_wqkr[(size_t)DIMM * (2 * DIMM)];
__device__ float g_wor[(size_t)DIMM * DIMM];

// ---------------------------------------------------------------------------
// helpers
// ---------------------------------------------------------------------------
__device__ __forceinline__ unsigned f2tf32(float x) {
    unsigned u;
    asm("cvt.rna.tf32.f32 %0, %1;" : "=r"(u) : "f"(x));
    return u;
}

__device__ __forceinline__ void mma_tf32(
    float& c0, float& c1, float& c2, float& c3,
    unsigned a0, unsigned a1, unsigned a2, unsigned a3,
    unsigned b0, unsigned b1)
{
    asm volatile(
        "mma.sync.aligned.m16n8k8.row.col.f32.tf32.tf32.f32 "
        "{%0,%1,%2,%3}, {%4,%5,%6,%7}, {%8,%9}, {%0,%1,%2,%3};"
        : "+f"(c0), "+f"(c1), "+f"(c2), "+f"(c3)
        : "r"(a0), "r"(a1), "r"(a2), "r"(a3), "r"(b0), "r"(b1));
}

__device__ __forceinline__ void cp_async16(void* smem, const void* gmem) {
    unsigned saddr = (unsigned)__cvta_generic_to_shared(smem);
    asm volatile("cp.async.cg.shared.global [%0], [%1], 16;"
                 :: "r"(saddr), "l"(gmem));
}

__device__ __forceinline__ void ldsm_x4(
    unsigned& r0, unsigned& r1, unsigned& r2, unsigned& r3, const void* p)
{
    unsigned a = (unsigned)__cvta_generic_to_shared(p);
    asm volatile("ldmatrix.sync.aligned.m8n8.x4.shared.b16 {%0,%1,%2,%3}, [%4];"
                 : "=r"(r0), "=r"(r1), "=r"(r2), "=r"(r3) : "r"(a));
}

// ---------------------------------------------------------------------------
// Fused elementwise tf32 pre-round of x, W_qk, W_out (one launch)
// ---------------------------------------------------------------------------
__global__ void __launch_bounds__(256) round3_kernel(
    const float* __restrict__ s0, float* __restrict__ d0, int n0,
    const float* __restrict__ s1, float* __restrict__ d1, int n1,
    const float* __restrict__ s2, float* __restrict__ d2, int n2)
{
    int i = blockIdx.x * 256 + threadIdx.x;
    const float* s; float* d; int j = i;
    if (j < n0)                { s = s0; d = d0; }
    else if ((j -= n0) < n1)   { s = s1; d = d1; }
    else if ((j -= n1) < n2)   { s = s2; d = d2; }
    else return;
    float4 v = ((const float4*)s)[j];
    float4 o;
    o.x = __uint_as_float(f2tf32(v.x));
    o.y = __uint_as_float(f2tf32(v.y));
    o.z = __uint_as_float(f2tf32(v.z));
    o.w = __uint_as_float(f2tf32(v.w));
    ((float4*)d)[j] = o;
}

// ---------------------------------------------------------------------------
// tf32 GEMM (unchanged from R8): 128x128 tile, BK=16, 3-stage cp.async,
// A-frags via ldmatrix.x4.
// ---------------------------------------------------------------------------
#define AS_STR 20
#define BS_STR 136

template <bool ROUND_OUT>
__global__ void __launch_bounds__(256) tgemm_kernel(
    const float* __restrict__ A, const float* __restrict__ B,
    float* __restrict__ C, int M, int N, int K)
{
    __shared__ float As[3][128][AS_STR];
    __shared__ float Bs[3][16][BS_STR];

    const int tid  = threadIdx.x;
    const int w    = tid >> 5;
    const int lane = tid & 31;
    const int g    = lane >> 2;
    const int t    = lane & 3;
    const int wm   = (w & 3) * 32;
    const int wn   = (w >> 2) * 64;

    const int mbase = blockIdx.y * 128;
    const int nbase = blockIdx.x * 128;

    const int arow0 = tid >> 2,         acc0 = (tid & 3) * 4;
    const int arow1 = (tid + 256) >> 2, acc1 = ((tid + 256) & 3) * 4;
    const int brow0 = tid >> 5,         bcc0 = (tid & 31) * 4;
    const int brow1 = (tid + 256) >> 5, bcc1 = ((tid + 256) & 31) * 4;

    const int lrow = (lane & 7) + ((lane >> 3) & 1) * 8;
    const int lcol = (lane >> 4) * 4;

    float acc[2][8][4];
#pragma unroll
    for (int mt = 0; mt < 2; mt++)
#pragma unroll
        for (int nt = 0; nt < 8; nt++)
#pragma unroll
            for (int j = 0; j < 4; j++) acc[mt][nt][j] = 0.f;

    const int NIT = K / 16;

#pragma unroll
    for (int s = 0; s < 2; s++) {
        const int k0 = s * 16;
        cp_async16(&As[s][arow0][acc0], A + (size_t)(mbase + arow0) * K + k0 + acc0);
        cp_async16(&As[s][arow1][acc1], A + (size_t)(mbase + arow1) * K + k0 + acc1);
        cp_async16(&Bs[s][brow0][bcc0], B + (size_t)(k0 + brow0) * N + nbase + bcc0);
        cp_async16(&Bs[s][brow1][bcc1], B + (size_t)(k0 + brow1) * N + nbase + bcc1);
        asm volatile("cp.async.commit_group;");
    }

    int buf = 0;
    for (int it = 0; it < NIT; it++) {
        if (it + 1 < NIT)
            asm volatile("cp.async.wait_group 1;");
        else
            asm volatile("cp.async.wait_group 0;");
        __syncthreads();

        unsigned af[2][2][4];
#pragma unroll
        for (int kc = 0; kc < 2; kc++)
#pragma unroll
            for (int mt = 0; mt < 2; mt++)
                ldsm_x4(af[kc][mt][0], af[kc][mt][1], af[kc][mt][2], af[kc][mt][3],
                        &As[buf][wm + mt * 16 + lrow][kc * 8 + lcol]);

#pragma unroll
        for (int kc = 0; kc < 2; kc++) {
#pragma unroll
            for (int nt = 0; nt < 8; nt++) {
                unsigned b0 = __float_as_uint(Bs[buf][kc * 8 + t][wn + nt * 8 + g]);
                unsigned b1 = __float_as_uint(Bs[buf][kc * 8 + t + 4][wn + nt * 8 + g]);
                mma_tf32(acc[0][nt][0], acc[0][nt][1], acc[0][nt][2], acc[0][nt][3],
                         af[kc][0][0], af[kc][0][1], af[kc][0][2], af[kc][0][3], b0, b1);
                mma_tf32(acc[1][nt][0], acc[1][nt][1], acc[1][nt][2], acc[1][nt][3],
                         af[kc][1][0], af[kc][1][1], af[kc][1][2], af[kc][1][3], b0, b1);
            }
        }

        if (it + 2 < NIT) {
            const int k0 = (it + 2) * 16;
            const int nb = (it + 2) % 3;
            cp_async16(&As[nb][arow0][acc0], A + (size_t)(mbase + arow0) * K + k0 + acc0);
            cp_async16(&As[nb][arow1][acc1], A + (size_t)(mbase + arow1) * K + k0 + acc1);
            cp_async16(&Bs[nb][brow0][bcc0], B + (size_t)(k0 + brow0) * N + nbase + bcc0);
            cp_async16(&Bs[nb][brow1][bcc1], B + (size_t)(k0 + brow1) * N + nbase + bcc1);
            asm volatile("cp.async.commit_group;");
        }
        __syncthreads();
        buf = (buf + 1 == 3) ? 0 : buf + 1;
    }

#pragma unroll
    for (int mt = 0; mt < 2; mt++) {
        const int r0 = mbase + wm + mt * 16 + g;
#pragma unroll
        for (int nt = 0; nt < 8; nt++) {
            const int col = nbase + wn + nt * 8 + 2 * t;
            float v0 = acc[mt][nt][0], v1 = acc[mt][nt][1];
            float v2 = acc[mt][nt][2], v3 = acc[mt][nt][3];
            if (ROUND_OUT) {
                v0 = __uint_as_float(f2tf32(v0));
                v1 = __uint_as_float(f2tf32(v1));
                v2 = __uint_as_float(f2tf32(v2));
                v3 = __uint_as_float(f2tf32(v3));
            }
            *(float2*)(C + (size_t)r0 * N + col)       = make_float2(v0, v1);
            *(float2*)(C + (size_t)(r0 + 8) * N + col) = make_float2(v2, v3);
        }
    }
}

// ---------------------------------------------------------------------------
// Tensor-core causal flash attention v4.
// 256 threads / 8 warps / 128 q-rows per phase; each block runs two balanced
// q-tiles {bx, NQT-1-bx}. K tile (Ks) via cp.async; transposed V tile (VsT)
// via reg-prefetched LDG + STS.128; P staged through per-warp SMEM + ldmatrix.
// ---------------------------------------------------------------------------
#define KS_STR 68
#define PS_STR 68
#define KS_ELEMS  (2 * 64 * KS_STR)   // double-buffered K
#define VST_ELEMS (2 * 64 * KS_STR)   // double-buffered V^T
#define PS_ELEMS  (8 * 16 * PS_STR)   // per-warp P tiles
#define ATTN_SMEM_BYTES ((KS_ELEMS + VST_ELEMS + PS_ELEMS) * 4)  // 104448 B

__global__ void __launch_bounds__(256, 2) attn_tc_kernel(
    const float* __restrict__ qk, float* __restrict__ out)
{
    extern __shared__ float sm[];
    float* Ks  = sm;                          // [2][64][KS_STR]  (key, d)
    float* VsT = sm + KS_ELEMS;               // [2][64][KS_STR]  (d, key)
    float* Ps  = sm + KS_ELEMS + VST_ELEMS;   // [8][16][PS_STR]  per-warp P

    const int bx = blockIdx.x, h = blockIdx.y, bb = blockIdx.z;
    const int tid  = threadIdx.x;
    const int w    = tid >> 5;
    const int lane = tid & 31;
    const int g    = lane >> 2;
    const int t    = lane & 3;

    // ldmatrix lane mappings
    const int lrow   = (lane & 7) + ((lane >> 3) & 1) * 8;  // A-frag row-in-16
    const int lcol   = (lane >> 4) * 4;                     // A-frag col 0/4
    const int ld_key = lane & 7;                            // S-stage B
    const int ld_d   = (lane >> 3) * 4;

    // V-transpose loader mapping: this thread owns column d, 16 keys
    const int vd = tid & 63;           // d (0..63)
    const int vk = (tid >> 6) * 16;    // key base (0,16,32,48)

    float* Pw = Ps + w * 16 * PS_STR;  // this warp's P tile

    const float* kbase = qk + (size_t)bb * N_TOK * (2 * DIMM) + DIMM + h * DHEAD;

#define FILL_KS(KT, BUF)                                                       \
    {                                                                          \
        _Pragma("unroll")                                                      \
        for (int i = tid; i < 64 * 16; i += 256) {                             \
            int r = i >> 4, c = (i & 15) * 4;                                  \
            cp_async16(&Ks[((BUF) * 64 + r) * KS_STR + c],                     \
                       kbase + (size_t)((KT) * 64 + r) * (2 * DIMM) + c);      \
        }                                                                      \
        asm volatile("cp.async.commit_group;");                                \
    }
    // coalesced column loads for V^T (lane spans d)
#define LDGV(KT, VREG)                                                         \
    {                                                                          \
        _Pragma("unroll")                                                      \
        for (int j = 0; j < 16; j++)                                           \
            VREG[j] = kbase[(size_t)((KT) * 64 + vk + j) * (2 * DIMM) + vd];   \
    }

    for (int phase = 0; phase < 2; phase++) {
        const int qt = (phase == 0) ? bx : (NQT - 1 - bx);

        const int qrow0 = bb * N_TOK + qt * 128 + w * 16;
        unsigned qf[8][4];
#pragma unroll
        for (int kc = 0; kc < 8; kc++) {
            const float* qp  = qk + (size_t)(qrow0 + g) * (2 * DIMM) + h * DHEAD + kc * 8;
            const float* qp8 = qp + (size_t)8 * (2 * DIMM);
            qf[kc][0] = __float_as_uint(qp[t]      * BETA_V);
            qf[kc][1] = __float_as_uint(qp8[t]     * BETA_V);
            qf[kc][2] = __float_as_uint(qp[t + 4]  * BETA_V);
            qf[kc][3] = __float_as_uint(qp8[t + 4] * BETA_V);
        }

        float o[8][4];
#pragma unroll
        for (int nt = 0; nt < 8; nt++)
#pragma unroll
            for (int j = 0; j < 4; j++) o[nt][j] = 0.f;
        float m0 = -1e30f, m1 = -1e30f, l0 = 0.f, l1 = 0.f;

        const int ktmax = 2 * qt + 1;
        const int diagw = 2 * qt + (w >> 2);

        float vreg[16];
        FILL_KS(0, 0);
        LDGV(0, vreg);

        for (int kt = 0; kt <= ktmax; kt++) {
            const int buf = kt & 1;
            if (kt + 1 <= ktmax) {
                FILL_KS(kt + 1, buf ^ 1);
                asm volatile("cp.async.wait_group 1;");
            } else {
                asm volatile("cp.async.wait_group 0;");
            }

            // store V^T for this tile from prefetched regs (STS.128, conflict-free)
            {
                float* vrow = &VsT[(buf * 64 + vd) * KS_STR + vk];
#pragma unroll
                for (int u = 0; u < 4; u++)
                    *(float4*)(vrow + 4 * u) = make_float4(
                        vreg[4 * u], vreg[4 * u + 1], vreg[4 * u + 2], vreg[4 * u + 3]);
            }
            __syncthreads();

            if (kt + 1 <= ktmax) LDGV(kt + 1, vreg);

            if (kt <= diagw) {
                // ---- S = Q @ K^T ----
                const float* ldb = Ks + (buf * 64 + ld_key) * KS_STR + ld_d;
                float sc[8][4];
#pragma unroll
                for (int nt = 0; nt < 8; nt++) {
                    sc[nt][0] = sc[nt][1] = sc[nt][2] = sc[nt][3] = 0.f;
#pragma unroll
                    for (int q = 0; q < 4; q++) {
                        unsigned b0, b1, b2, b3;
                        ldsm_x4(b0, b1, b2, b3, ldb + nt * 8 * KS_STR + 16 * q);
                        mma_tf32(sc[nt][0], sc[nt][1], sc[nt][2], sc[nt][3],
                                 qf[2 * q][0], qf[2 * q][1], qf[2 * q][2], qf[2 * q][3],
                                 b0, b1);
                        mma_tf32(sc[nt][0], sc[nt][1], sc[nt][2], sc[nt][3],
                                 qf[2 * q + 1][0], qf[2 * q + 1][1],
                                 qf[2 * q + 1][2], qf[2 * q + 1][3], b2, b3);
                    }
                }

                // ---- causal mask (warp's diagonal tile only) ----
                if (kt == diagw) {
                    const int lr0 = w * 16 + g, lr1 = lr0 + 8;
                    const int cb  = (w >> 2) * 64;
#pragma unroll
                    for (int nt = 0; nt < 8; nt++) {
                        int col = cb + nt * 8 + 2 * t;
                        if (col     > lr0) sc[nt][0] = -1e30f;
                        if (col + 1 > lr0) sc[nt][1] = -1e30f;
                        if (col     > lr1) sc[nt][2] = -1e30f;
                        if (col + 1 > lr1) sc[nt][3] = -1e30f;
                    }
                }

                // ---- online softmax ----
                float tmax0 = -1e30f, tmax1 = -1e30f;
#pragma unroll
                for (int nt = 0; nt < 8; nt++) {
                    tmax0 = fmaxf(tmax0, fmaxf(sc[nt][0], sc[nt][1]));
                    tmax1 = fmaxf(tmax1, fmaxf(sc[nt][2], sc[nt][3]));
                }
                tmax0 = fmaxf(tmax0, __shfl_xor_sync(0xffffffffu, tmax0, 1));
                tmax0 = fmaxf(tmax0, __shfl_xor_sync(0xffffffffu, tmax0, 2));
                tmax1 = fmaxf(tmax1, __shfl_xor_sync(0xffffffffu, tmax1, 1));
                tmax1 = fmaxf(tmax1, __shfl_xor_sync(0xffffffffu, tmax1, 2));

                float mn0 = fmaxf(m0, tmax0), mn1 = fmaxf(m1, tmax1);
                float corr0 = __expf(m0 - mn0), corr1 = __expf(m1 - mn1);
                m0 = mn0; m1 = mn1;

                float ls0 = 0.f, ls1 = 0.f;
#pragma unroll
                for (int nt = 0; nt < 8; nt++) {
                    float p0 = __expf(sc[nt][0] - mn0);
                    float p1 = __expf(sc[nt][1] - mn0);
                    float p2 = __expf(sc[nt][2] - mn1);
                    float p3 = __expf(sc[nt][3] - mn1);
                    ls0 += p0 + p1;
                    ls1 += p2 + p3;
                    // stage P in per-warp smem (tf32-rounded)
                    *(float2*)&Pw[g * PS_STR + nt * 8 + 2 * t] = make_float2(
                        __uint_as_float(f2tf32(p0)), __uint_as_float(f2tf32(p1)));
                    *(float2*)&Pw[(g + 8) * PS_STR + nt * 8 + 2 * t] = make_float2(
                        __uint_as_float(f2tf32(p2)), __uint_as_float(f2tf32(p3)));
                }
                ls0 += __shfl_xor_sync(0xffffffffu, ls0, 1);
                ls0 += __shfl_xor_sync(0xffffffffu, ls0, 2);
                ls1 += __shfl_xor_sync(0xffffffffu, ls1, 1);
                ls1 += __shfl_xor_sync(0xffffffffu, ls1, 2);
                l0 = l0 * corr0 + ls0;
                l1 = l1 * corr1 + ls1;

#pragma unroll
                for (int nt = 0; nt < 8; nt++) {
                    o[nt][0] *= corr0; o[nt][1] *= corr0;
                    o[nt][2] *= corr1; o[nt][3] *= corr1;
                }
                __syncwarp();

                // ---- O += P @ V : A-frags from Ps (ldmatrix), B from VsT ----
                const float* vtb = VsT + buf * 64 * KS_STR;
#pragma unroll
                for (int q = 0; q < 4; q++) {
                    unsigned a0[4], a1[4];
                    ldsm_x4(a0[0], a0[1], a0[2], a0[3],
                            &Pw[lrow * PS_STR + (2 * q) * 8 + lcol]);
                    ldsm_x4(a1[0], a1[1], a1[2], a1[3],
                            &Pw[lrow * PS_STR + (2 * q + 1) * 8 + lcol]);
#pragma unroll
                    for (int nt = 0; nt < 8; nt++) {
                        unsigned b0, b1, b2, b3;
                        ldsm_x4(b0, b1, b2, b3,
                                vtb + (nt * 8 + ld_key) * KS_STR + q * 16 + ld_d);
                        mma_tf32(o[nt][0], o[nt][1], o[nt][2], o[nt][3],
                                 a0[0], a0[1], a0[2], a0[3], b0, b1);
                        mma_tf32(o[nt][0], o[nt][1], o[nt][2], o[nt][3],
                                 a1[0], a1[1], a1[2], a1[3], b2, b3);
                    }
                }
            }
            __syncthreads();
        }

        // ---- epilogue: normalize, round to tf32 (feeds GEMM2), store ----
        const float inv0 = 1.f / l0, inv1 = 1.f / l1;
        float* op0 = out + (size_t)(qrow0 + g) * DIMM + h * DHEAD;
        float* op1 = op0 + (size_t)8 * DIMM;
#pragma unroll
        for (int nt = 0; nt < 8; nt++) {
            *(float2*)(op0 + nt * 8 + 2 * t) = make_float2(
                __uint_as_float(f2tf32(o[nt][0] * inv0)),
                __uint_as_float(f2tf32(o[nt][1] * inv0)));
            *(float2*)(op1 + nt * 8 + 2 * t) = make_float2(
                __uint_as_float(f2tf32(o[nt][2] * inv1)),
                __uint_as_float(f2tf32(o[nt][3] * inv1)));
        }
        __syncthreads();   // protect smem before next phase refills
    }
#undef FILL_KS
#undef LDGV
}

// ---------------------------------------------------------------------------
extern "C" void kernel_launch(void* const* d_in, const int* in_sizes, int n_in,
                              void* d_out, int out_size)
{
    const float* x     = (const float*)d_in[0];
    const float* W_qk  = (const float*)d_in[1];
    const float* W_out = (const float*)d_in[2];
    float* out = (float*)d_out;

    float *qkbuf, *aobuf, *xr, *wqkr, *wor;
    cudaGetSymbolAddress((void**)&qkbuf, g_qk);
    cudaGetSymbolAddress((void**)&aobuf, g_ao);
    cudaGetSymbolAddress((void**)&xr,    g_xr);
    cudaGetSymbolAddress((void**)&wqkr,  g_wqkr);
    cudaGetSymbolAddress((void**)&wor,   g_wor);

    static bool attr_set = false;
    if (!attr_set) {
        cudaFuncSetAttribute(attn_tc_kernel,
                             cudaFuncAttributeMaxDynamicSharedMemorySize,
                             ATTN_SMEM_BYTES);
        attr_set = true;
    }

    const int nx  = NBATCH * N_TOK * DIMM / 4;
    const int nwq = DIMM * 2 * DIMM / 4;
    const int nwo = DIMM * DIMM / 4;
    const int ntot = nx + nwq + nwo;
    round3_kernel<<<(ntot + 255) / 256, 256>>>(x, xr, nx, W_qk, wqkr, nwq,
                                               W_out, wor, nwo);

    // qk = x @ W_qk (tf32-rounded output feeds attention)
    tgemm_kernel<true><<<dim3((2 * DIMM) / 128, (NBATCH * N_TOK) / 128), 256>>>(
        xr, wqkr, qkbuf, NBATCH * N_TOK, 2 * DIMM, DIMM);
    // causal attention, balanced q-tile pairs {bx, 15-bx}
    attn_tc_kernel<<<dim3(NQT / 2, NHEAD, NBATCH), 256, ATTN_SMEM_BYTES>>>(
        qkbuf, aobuf);
    // out = ao @ W_out
    tgemm_kernel<false><<<dim3(DIMM / 128, (NBATCH * N_TOK) / 128), 256>>>(
        aobuf, wor, out, NBATCH * N_TOK, DIMM, DIMM);
}

// round 13
// speedup vs baseline: 1.9104x; 1.7122x over previous
#include <cuda_runtime.h>
#include <cuda_fp16.h>
#include <math.h>
#include <stdint.h>

#define N_TOK  2048
#define DIMM   1024
#define NBATCH 2
#define NHEAD  16
#define DHEAD  64
#define BETA_V 0.125f
#define NQT    (N_TOK / 128)

// Scratch (static device allocations — no cudaMalloc anywhere)
__device__ __half g_qkh[(size_t)(NBATCH * N_TOK) * (2 * DIMM)];  // 16 MB
__device__ __half g_aoh[(size_t)(NBATCH * N_TOK) * DIMM];        //  8 MB
__device__ __half g_xh[(size_t)(NBATCH * N_TOK) * DIMM];         //  8 MB
__device__ __half g_wqkh[(size_t)DIMM * (2 * DIMM)];             //  4 MB
__device__ __half g_woh[(size_t)DIMM * DIMM];                    //  2 MB

// ---------------------------------------------------------------------------
// helpers
// ---------------------------------------------------------------------------
__device__ __forceinline__ void mma_f16(
    float& c0, float& c1, float& c2, float& c3,
    unsigned a0, unsigned a1, unsigned a2, unsigned a3,
    unsigned b0, unsigned b1)
{
    asm volatile(
        "mma.sync.aligned.m16n8k16.row.col.f32.f16.f16.f32 "
        "{%0,%1,%2,%3}, {%4,%5,%6,%7}, {%8,%9}, {%0,%1,%2,%3};"
        : "+f"(c0), "+f"(c1), "+f"(c2), "+f"(c3)
        : "r"(a0), "r"(a1), "r"(a2), "r"(a3), "r"(b0), "r"(b1));
}

__device__ __forceinline__ void cp_async16(void* smem, const void* gmem) {
    unsigned saddr = (unsigned)__cvta_generic_to_shared(smem);
    asm volatile("cp.async.cg.shared.global [%0], [%1], 16;"
                 :: "r"(saddr), "l"(gmem));
}

__device__ __forceinline__ void ldsm_x4(
    unsigned& r0, unsigned& r1, unsigned& r2, unsigned& r3, const void* p)
{
    unsigned a = (unsigned)__cvta_generic_to_shared(p);
    asm volatile("ldmatrix.sync.aligned.m8n8.x4.shared.b16 {%0,%1,%2,%3}, [%4];"
                 : "=r"(r0), "=r"(r1), "=r"(r2), "=r"(r3) : "r"(a));
}

__device__ __forceinline__ void ldsm_x4t(
    unsigned& r0, unsigned& r1, unsigned& r2, unsigned& r3, const void* p)
{
    unsigned a = (unsigned)__cvta_generic_to_shared(p);
    asm volatile("ldmatrix.sync.aligned.m8n8.x4.trans.shared.b16 {%0,%1,%2,%3}, [%4];"
                 : "=r"(r0), "=r"(r1), "=r"(r2), "=r"(r3) : "r"(a));
}

__device__ __forceinline__ unsigned h2u(__half2 v) {
    return *reinterpret_cast<unsigned*>(&v);
}

// ---------------------------------------------------------------------------
// Fused fp32 -> fp16 convert of x, W_qk, W_out (one launch); n in float4 units
// ---------------------------------------------------------------------------
__global__ void __launch_bounds__(256) conv3_kernel(
    const float* __restrict__ s0, __half* __restrict__ d0, int n0,
    const float* __restrict__ s1, __half* __restrict__ d1, int n1,
    const float* __restrict__ s2, __half* __restrict__ d2, int n2)
{
    int i = blockIdx.x * 256 + threadIdx.x;
    const float* s; __half* d; int j = i;
    if (j < n0)                { s = s0; d = d0; }
    else if ((j -= n0) < n1)   { s = s1; d = d1; }
    else if ((j -= n1) < n2)   { s = s2; d = d2; }
    else return;
    float4 v = ((const float4*)s)[j];
    __half2 lo = __floats2half2_rn(v.x, v.y);
    __half2 hi = __floats2half2_rn(v.z, v.w);
    ((__half2*)d)[2 * j]     = lo;
    ((__half2*)d)[2 * j + 1] = hi;
}

// ---------------------------------------------------------------------------
// fp16 GEMM: C[M,N] = A[M,K] @ B[K,N]. A,B fp16; accum fp32.
// 128x128 tile, BK=16, 8 warps x (32x64), 3-stage cp.async.
// A-frags ldmatrix.x4 on [m][k]; B-frags ldmatrix.x4.trans on [k][n].
// OUT_HALF: store fp16 (feeds next fp16 stage); else fp32.
// ---------------------------------------------------------------------------
#define AS_STRH 24    // halves; row stride 48B (conflict-free ldmatrix)
#define BS_STRH 136   // halves; row stride 272B =16 mod 128 (conflict-free)

template <bool OUT_HALF>
__global__ void __launch_bounds__(256) hgemm_kernel(
    const __half* __restrict__ A, const __half* __restrict__ B,
    void* __restrict__ Cv, int M, int N, int K)
{
    __shared__ __half As[3][128][AS_STRH];
    __shared__ __half Bs[3][16][BS_STRH];

    const int tid  = threadIdx.x;
    const int w    = tid >> 5;
    const int lane = tid & 31;
    const int g    = lane >> 2;
    const int t    = lane & 3;
    const int wm   = (w & 3) * 32;
    const int wn   = (w >> 2) * 64;

    const int mbase = blockIdx.y * 128;
    const int nbase = blockIdx.x * 128;

    // loaders: A 256 chunks (1/thread), B 256 chunks (1/thread), 16B each
    const int arow = tid >> 1, acol = (tid & 1) * 8;
    const int brow = tid >> 4, bcol = (tid & 15) * 8;

    // ldmatrix lane mappings
    const int lrow = (lane & 7) + ((lane >> 3) & 1) * 8;
    const int lcol = (lane >> 4) * 8;                       // halves
    const int tkrow = (lane & 7) + ((lane >> 3) & 1) * 8;   // B trans: k row
    const int tncol = (lane >> 4) * 8;                      // B trans: n offset

    float acc[2][8][4];
#pragma unroll
    for (int mt = 0; mt < 2; mt++)
#pragma unroll
        for (int nt = 0; nt < 8; nt++)
#pragma unroll
            for (int j = 0; j < 4; j++) acc[mt][nt][j] = 0.f;

    const int NIT = K / 16;

#pragma unroll
    for (int s = 0; s < 2; s++) {
        const int k0 = s * 16;
        cp_async16(&As[s][arow][acol], A + (size_t)(mbase + arow) * K + k0 + acol);
        cp_async16(&Bs[s][brow][bcol], B + (size_t)(k0 + brow) * N + nbase + bcol);
        asm volatile("cp.async.commit_group;");
    }

    int buf = 0;
    for (int it = 0; it < NIT; it++) {
        if (it + 1 < NIT)
            asm volatile("cp.async.wait_group 1;");
        else
            asm volatile("cp.async.wait_group 0;");
        __syncthreads();

        unsigned af[2][4];
#pragma unroll
        for (int mt = 0; mt < 2; mt++)
            ldsm_x4(af[mt][0], af[mt][1], af[mt][2], af[mt][3],
                    &As[buf][wm + mt * 16 + lrow][lcol]);

#pragma unroll
        for (int ntp = 0; ntp < 4; ntp++) {
            unsigned b[4];
            ldsm_x4t(b[0], b[1], b[2], b[3],
                     &Bs[buf][tkrow][wn + ntp * 16 + tncol]);
#pragma unroll
            for (int mt = 0; mt < 2; mt++) {
                mma_f16(acc[mt][2 * ntp][0], acc[mt][2 * ntp][1],
                        acc[mt][2 * ntp][2], acc[mt][2 * ntp][3],
                        af[mt][0], af[mt][1], af[mt][2], af[mt][3], b[0], b[1]);
                mma_f16(acc[mt][2 * ntp + 1][0], acc[mt][2 * ntp + 1][1],
                        acc[mt][2 * ntp + 1][2], acc[mt][2 * ntp + 1][3],
                        af[mt][0], af[mt][1], af[mt][2], af[mt][3], b[2], b[3]);
            }
        }

        if (it + 2 < NIT) {
            const int k0 = (it + 2) * 16;
            const int nb = (it + 2) % 3;
            cp_async16(&As[nb][arow][acol], A + (size_t)(mbase + arow) * K + k0 + acol);
            cp_async16(&Bs[nb][brow][bcol], B + (size_t)(k0 + brow) * N + nbase + bcol);
            asm volatile("cp.async.commit_group;");
        }
        __syncthreads();
        buf = (buf + 1 == 3) ? 0 : buf + 1;
    }

#pragma unroll
    for (int mt = 0; mt < 2; mt++) {
        const int r0 = mbase + wm + mt * 16 + g;
#pragma unroll
        for (int nt = 0; nt < 8; nt++) {
            const int col = nbase + wn + nt * 8 + 2 * t;
            if (OUT_HALF) {
                __half* Ch = (__half*)Cv;
                *(__half2*)(Ch + (size_t)r0 * N + col) =
                    __floats2half2_rn(acc[mt][nt][0], acc[mt][nt][1]);
                *(__half2*)(Ch + (size_t)(r0 + 8) * N + col) =
                    __floats2half2_rn(acc[mt][nt][2], acc[mt][nt][3]);
            } else {
                float* Cf = (float*)Cv;
                *(float2*)(Cf + (size_t)r0 * N + col) =
                    make_float2(acc[mt][nt][0], acc[mt][nt][1]);
                *(float2*)(Cf + (size_t)(r0 + 8) * N + col) =
                    make_float2(acc[mt][nt][2], acc[mt][nt][3]);
            }
        }
    }
}

// ---------------------------------------------------------------------------
// fp16 tensor-core causal flash attention.
// 256 threads / 8 warps / 128 q-rows per phase; two balanced q-tiles per block.
// Ks [key][d] fp16 (cp.async), VsT [d][key] fp16 (reg-prefetch LDG + STS),
// Pw per-warp [m][key] fp16. All fragments via ldmatrix (strides 144B).
// ---------------------------------------------------------------------------
#define KS_STRH 72
#define VS_STRH 72
#define PS_STRH 72
#define KS_HALVES  (2 * 64 * KS_STRH)
#define VST_HALVES (2 * 64 * VS_STRH)
#define PS_HALVES  (8 * 16 * PS_STRH)
#define ATTN_SMEM_BYTES ((KS_HALVES + VST_HALVES + PS_HALVES) * 2)  // 55296 B

__global__ void __launch_bounds__(256, 2) attn_tc_kernel(
    const __half* __restrict__ qk, __half* __restrict__ out)
{
    extern __shared__ __half smh[];
    __half* Ks  = smh;
    __half* VsT = smh + KS_HALVES;
    __half* Ps  = smh + KS_HALVES + VST_HALVES;

    const int bx = blockIdx.x, h = blockIdx.y, bb = blockIdx.z;
    const int tid  = threadIdx.x;
    const int w    = tid >> 5;
    const int lane = tid & 31;
    const int g    = lane >> 2;
    const int t    = lane & 3;

    const int lrow = (lane & 7) + ((lane >> 3) & 1) * 8;  // A-frag rows
    const int lcol = (lane >> 4) * 8;                     // A-frag k-offset

    const int vd = tid & 63;
    const int vk = (tid >> 6) * 16;

    __half* Pw = Ps + w * 16 * PS_STRH;
    const __half2 beta2 = __float2half2_rn(BETA_V);

    const __half* kbase = qk + (size_t)bb * N_TOK * (2 * DIMM) + DIMM + h * DHEAD;

#define FILL_KS(KT, BUF)                                                       \
    {                                                                          \
        _Pragma("unroll")                                                      \
        for (int i = tid; i < 64 * 8; i += 256) {                              \
            int r = i >> 3, c = (i & 7) * 8;                                   \
            cp_async16(&Ks[((BUF) * 64 + r) * KS_STRH + c],                    \
                       kbase + (size_t)((KT) * 64 + r) * (2 * DIMM) + c);      \
        }                                                                      \
        asm volatile("cp.async.commit_group;");                                \
    }
#define LDGV(KT, VREG)                                                         \
    {                                                                          \
        _Pragma("unroll")                                                      \
        for (int j = 0; j < 16; j++)                                           \
            VREG[j] = kbase[(size_t)((KT) * 64 + vk + j) * (2 * DIMM) + vd];   \
    }

    for (int phase = 0; phase < 2; phase++) {
        const int qt = (phase == 0) ? bx : (NQT - 1 - bx);

        const int qrow0 = bb * N_TOK + qt * 128 + w * 16;
        // Q fragments: 4 chunks of k16, beta-scaled (exact: 2^-3)
        unsigned qf[4][4];
        {
            const __half* qp  = qk + (size_t)(qrow0 + g) * (2 * DIMM) + h * DHEAD;
            const __half* qp8 = qp + (size_t)8 * (2 * DIMM);
#pragma unroll
            for (int kc = 0; kc < 4; kc++) {
                __half2 a0 = *(const __half2*)(qp  + kc * 16 + 2 * t);
                __half2 a1 = *(const __half2*)(qp8 + kc * 16 + 2 * t);
                __half2 a2 = *(const __half2*)(qp  + kc * 16 + 8 + 2 * t);
                __half2 a3 = *(const __half2*)(qp8 + kc * 16 + 8 + 2 * t);
                qf[kc][0] = h2u(__hmul2(a0, beta2));
                qf[kc][1] = h2u(__hmul2(a1, beta2));
                qf[kc][2] = h2u(__hmul2(a2, beta2));
                qf[kc][3] = h2u(__hmul2(a3, beta2));
            }
        }

        float o[8][4];
#pragma unroll
        for (int nt = 0; nt < 8; nt++)
#pragma unroll
            for (int j = 0; j < 4; j++) o[nt][j] = 0.f;
        float m0 = -1e30f, m1 = -1e30f, l0 = 0.f, l1 = 0.f;

        const int ktmax = 2 * qt + 1;
        const int diagw = 2 * qt + (w >> 2);

        __half vreg[16];
        FILL_KS(0, 0);
        LDGV(0, vreg);

        for (int kt = 0; kt <= ktmax; kt++) {
            const int buf = kt & 1;
            if (kt + 1 <= ktmax) {
                FILL_KS(kt + 1, buf ^ 1);
                asm volatile("cp.async.wait_group 1;");
            } else {
                asm volatile("cp.async.wait_group 0;");
            }

            {
                __half* vrow = &VsT[(buf * 64 + vd) * VS_STRH + vk];
#pragma unroll
                for (int u = 0; u < 8; u++)
                    *(__half2*)(vrow + 2 * u) =
                        __halves2half2(vreg[2 * u], vreg[2 * u + 1]);
            }
            __syncthreads();

            if (kt + 1 <= ktmax) LDGV(kt + 1, vreg);

            if (kt <= diagw) {
                // ---- S = Q @ K^T : B-frags via 2x ldmatrix.x4 per nt ----
                float sc[8][4];
#pragma unroll
                for (int nt = 0; nt < 8; nt++) {
                    sc[nt][0] = sc[nt][1] = sc[nt][2] = sc[nt][3] = 0.f;
                    const __half* kr =
                        &Ks[(buf * 64 + nt * 8 + (lane & 7)) * KS_STRH + (lane >> 3) * 8];
                    unsigned b[4];
                    ldsm_x4(b[0], b[1], b[2], b[3], kr);
                    mma_f16(sc[nt][0], sc[nt][1], sc[nt][2], sc[nt][3],
                            qf[0][0], qf[0][1], qf[0][2], qf[0][3], b[0], b[1]);
                    mma_f16(sc[nt][0], sc[nt][1], sc[nt][2], sc[nt][3],
                            qf[1][0], qf[1][1], qf[1][2], qf[1][3], b[2], b[3]);
                    ldsm_x4(b[0], b[1], b[2], b[3], kr + 32);
                    mma_f16(sc[nt][0], sc[nt][1], sc[nt][2], sc[nt][3],
                            qf[2][0], qf[2][1], qf[2][2], qf[2][3], b[0], b[1]);
                    mma_f16(sc[nt][0], sc[nt][1], sc[nt][2], sc[nt][3],
                            qf[3][0], qf[3][1], qf[3][2], qf[3][3], b[2], b[3]);
                }

                // ---- causal mask (warp's diagonal tile only) ----
                if (kt == diagw) {
                    const int lr0 = w * 16 + g, lr1 = lr0 + 8;
                    const int cb  = (w >> 2) * 64;
#pragma unroll
                    for (int nt = 0; nt < 8; nt++) {
                        int col = cb + nt * 8 + 2 * t;
                        if (col     > lr0) sc[nt][0] = -1e30f;
                        if (col + 1 > lr0) sc[nt][1] = -1e30f;
                        if (col     > lr1) sc[nt][2] = -1e30f;
                        if (col + 1 > lr1) sc[nt][3] = -1e30f;
                    }
                }

                // ---- online softmax ----
                float tmax0 = -1e30f, tmax1 = -1e30f;
#pragma unroll
                for (int nt = 0; nt < 8; nt++) {
                    tmax0 = fmaxf(tmax0, fmaxf(sc[nt][0], sc[nt][1]));
                    tmax1 = fmaxf(tmax1, fmaxf(sc[nt][2], sc[nt][3]));
                }
                tmax0 = fmaxf(tmax0, __shfl_xor_sync(0xffffffffu, tmax0, 1));
                tmax0 = fmaxf(tmax0, __shfl_xor_sync(0xffffffffu, tmax0, 2));
                tmax1 = fmaxf(tmax1, __shfl_xor_sync(0xffffffffu, tmax1, 1));
                tmax1 = fmaxf(tmax1, __shfl_xor_sync(0xffffffffu, tmax1, 2));

                float mn0 = fmaxf(m0, tmax0), mn1 = fmaxf(m1, tmax1);
                float corr0 = __expf(m0 - mn0), corr1 = __expf(m1 - mn1);
                m0 = mn0; m1 = mn1;

                float ls0 = 0.f, ls1 = 0.f;
#pragma unroll
                for (int nt = 0; nt < 8; nt++) {
                    float p0 = __expf(sc[nt][0] - mn0);
                    float p1 = __expf(sc[nt][1] - mn0);
                    float p2 = __expf(sc[nt][2] - mn1);
                    float p3 = __expf(sc[nt][3] - mn1);
                    ls0 += p0 + p1;
                    ls1 += p2 + p3;
                    *(__half2*)&Pw[g * PS_STRH + nt * 8 + 2 * t] =
                        __floats2half2_rn(p0, p1);
                    *(__half2*)&Pw[(g + 8) * PS_STRH + nt * 8 + 2 * t] =
                        __floats2half2_rn(p2, p3);
                }
                ls0 += __shfl_xor_sync(0xffffffffu, ls0, 1);
                ls0 += __shfl_xor_sync(0xffffffffu, ls0, 2);
                ls1 += __shfl_xor_sync(0xffffffffu, ls1, 1);
                ls1 += __shfl_xor_sync(0xffffffffu, ls1, 2);
                l0 = l0 * corr0 + ls0;
                l1 = l1 * corr1 + ls1;

#pragma unroll
                for (int nt = 0; nt < 8; nt++) {
                    o[nt][0] *= corr0; o[nt][1] *= corr0;
                    o[nt][2] *= corr1; o[nt][3] *= corr1;
                }
                __syncwarp();

                // ---- O += P @ V : A from Pw, B from VsT (all ldmatrix) ----
#pragma unroll
                for (int kc = 0; kc < 4; kc++) {
                    unsigned ap[4];
                    ldsm_x4(ap[0], ap[1], ap[2], ap[3],
                            &Pw[lrow * PS_STRH + kc * 16 + lcol]);
#pragma unroll
                    for (int ntp = 0; ntp < 4; ntp++) {
                        unsigned b[4];
                        ldsm_x4(b[0], b[1], b[2], b[3],
                                &VsT[(buf * 64 + ntp * 16 + (lane >> 4) * 8 + (lane & 7))
                                         * VS_STRH
                                     + kc * 16 + ((lane >> 3) & 1) * 8]);
                        mma_f16(o[2 * ntp][0], o[2 * ntp][1],
                                o[2 * ntp][2], o[2 * ntp][3],
                                ap[0], ap[1], ap[2], ap[3], b[0], b[1]);
                        mma_f16(o[2 * ntp + 1][0], o[2 * ntp + 1][1],
                                o[2 * ntp + 1][2], o[2 * ntp + 1][3],
                                ap[0], ap[1], ap[2], ap[3], b[2], b[3]);
                    }
                }
            }
            __syncthreads();
        }

        // ---- epilogue: normalize, convert to fp16 (feeds GEMM2) ----
        const float inv0 = 1.f / l0, inv1 = 1.f / l1;
        __half* op0 = out + (size_t)(qrow0 + g) * DIMM + h * DHEAD;
        __half* op1 = op0 + (size_t)8 * DIMM;
#pragma unroll
        for (int nt = 0; nt < 8; nt++) {
            *(__half2*)(op0 + nt * 8 + 2 * t) =
                __floats2half2_rn(o[nt][0] * inv0, o[nt][1] * inv0);
            *(__half2*)(op1 + nt * 8 + 2 * t) =
                __floats2half2_rn(o[nt][2] * inv1, o[nt][3] * inv1);
        }
        __syncthreads();
    }
#undef FILL_KS
#undef LDGV
}

// ---------------------------------------------------------------------------
extern "C" void kernel_launch(void* const* d_in, const int* in_sizes, int n_in,
                              void* d_out, int out_size)
{
    const float* x     = (const float*)d_in[0];
    const float* W_qk  = (const float*)d_in[1];
    const float* W_out = (const float*)d_in[2];
    float* out = (float*)d_out;

    __half *qkh, *aoh, *xh, *wqkh, *woh;
    cudaGetSymbolAddress((void**)&qkh,  g_qkh);
    cudaGetSymbolAddress((void**)&aoh,  g_aoh);
    cudaGetSymbolAddress((void**)&xh,   g_xh);
    cudaGetSymbolAddress((void**)&wqkh, g_wqkh);
    cudaGetSymbolAddress((void**)&woh,  g_woh);

    static bool attr_set = false;
    if (!attr_set) {
        cudaFuncSetAttribute(attn_tc_kernel,
                             cudaFuncAttributeMaxDynamicSharedMemorySize,
                             ATTN_SMEM_BYTES);
        attr_set = true;
    }

    const int nx  = NBATCH * N_TOK * DIMM / 4;
    const int nwq = DIMM * 2 * DIMM / 4;
    const int nwo = DIMM * DIMM / 4;
    const int ntot = nx + nwq + nwo;
    conv3_kernel<<<(ntot + 255) / 256, 256>>>(x, xh, nx, W_qk, wqkh, nwq,
                                              W_out, woh, nwo);

    // qk = x @ W_qk  (fp16 in/out, fp32 accum)
    hgemm_kernel<true><<<dim3((2 * DIMM) / 128, (NBATCH * N_TOK) / 128), 256>>>(
        xh, wqkh, qkh, NBATCH * N_TOK, 2 * DIMM, DIMM);
    // causal attention (fp16 tiles, fp32 softmax/accum)
    attn_tc_kernel<<<dim3(NQT / 2, NHEAD, NBATCH), 256, ATTN_SMEM_BYTES>>>(
        qkh, aoh);
    // out = ao @ W_out  (fp16 in, fp32 out)
    hgemm_kernel<false><<<dim3(DIMM / 128, (NBATCH * N_TOK) / 128), 256>>>(
        aoh, woh, out, NBATCH * N_TOK, DIMM, DIMM);
}

// round 14
// speedup vs baseline: 2.0427x; 1.0692x over previous
#include <cuda_runtime.h>
#include <cuda_fp16.h>
#include <math.h>
#include <stdint.h>

#define N_TOK  2048
#define DIMM   1024
#define NBATCH 2
#define NHEAD  16
#define DHEAD  64
#define NQT    (N_TOK / 128)
#define BETA_LOG2E 0.1803368801111244f   /* 0.125 * log2(e) */

// Scratch (static device allocations — no cudaMalloc anywhere)
__device__ __half g_qkh[(size_t)(NBATCH * N_TOK) * (2 * DIMM)];
__device__ __half g_aoh[(size_t)(NBATCH * N_TOK) * DIMM];
__device__ __half g_xh[(size_t)(NBATCH * N_TOK) * DIMM];
__device__ __half g_wqkh[(size_t)DIMM * (2 * DIMM)];
__device__ __half g_woh[(size_t)DIMM * DIMM];

// ---------------------------------------------------------------------------
// helpers
// ---------------------------------------------------------------------------
__device__ __forceinline__ void mma_f16(
    float& c0, float& c1, float& c2, float& c3,
    unsigned a0, unsigned a1, unsigned a2, unsigned a3,
    unsigned b0, unsigned b1)
{
    asm volatile(
        "mma.sync.aligned.m16n8k16.row.col.f32.f16.f16.f32 "
        "{%0,%1,%2,%3}, {%4,%5,%6,%7}, {%8,%9}, {%0,%1,%2,%3};"
        : "+f"(c0), "+f"(c1), "+f"(c2), "+f"(c3)
        : "r"(a0), "r"(a1), "r"(a2), "r"(a3), "r"(b0), "r"(b1));
}

__device__ __forceinline__ void cp_async16(void* smem, const void* gmem) {
    unsigned saddr = (unsigned)__cvta_generic_to_shared(smem);
    asm volatile("cp.async.cg.shared.global [%0], [%1], 16;"
                 :: "r"(saddr), "l"(gmem));
}

__device__ __forceinline__ void ldsm_x4(
    unsigned& r0, unsigned& r1, unsigned& r2, unsigned& r3, const void* p)
{
    unsigned a = (unsigned)__cvta_generic_to_shared(p);
    asm volatile("ldmatrix.sync.aligned.m8n8.x4.shared.b16 {%0,%1,%2,%3}, [%4];"
                 : "=r"(r0), "=r"(r1), "=r"(r2), "=r"(r3) : "r"(a));
}

__device__ __forceinline__ void ldsm_x4t(
    unsigned& r0, unsigned& r1, unsigned& r2, unsigned& r3, const void* p)
{
    unsigned a = (unsigned)__cvta_generic_to_shared(p);
    asm volatile("ldmatrix.sync.aligned.m8n8.x4.trans.shared.b16 {%0,%1,%2,%3}, [%4];"
                 : "=r"(r0), "=r"(r1), "=r"(r2), "=r"(r3) : "r"(a));
}

__device__ __forceinline__ unsigned h2u(__half2 v) {
    return *reinterpret_cast<unsigned*>(&v);
}

// ---------------------------------------------------------------------------
// Fused fp32 -> fp16 convert of x, W_qk, W_out (one launch)
// ---------------------------------------------------------------------------
__global__ void __launch_bounds__(256) conv3_kernel(
    const float* __restrict__ s0, __half* __restrict__ d0, int n0,
    const float* __restrict__ s1, __half* __restrict__ d1, int n1,
    const float* __restrict__ s2, __half* __restrict__ d2, int n2)
{
    int i = blockIdx.x * 256 + threadIdx.x;
    const float* s; __half* d; int j = i;
    if (j < n0)                { s = s0; d = d0; }
    else if ((j -= n0) < n1)   { s = s1; d = d1; }
    else if ((j -= n1) < n2)   { s = s2; d = d2; }
    else return;
    float4 v = ((const float4*)s)[j];
    ((__half2*)d)[2 * j]     = __floats2half2_rn(v.x, v.y);
    ((__half2*)d)[2 * j + 1] = __floats2half2_rn(v.z, v.w);
}

// ---------------------------------------------------------------------------
// fp16 GEMM (unchanged from R13): 128x128 tile, BK=16, 3-stage cp.async.
// ---------------------------------------------------------------------------
#define AS_STRH 24
#define BS_STRH 136

template <bool OUT_HALF>
__global__ void __launch_bounds__(256) hgemm_kernel(
    const __half* __restrict__ A, const __half* __restrict__ B,
    void* __restrict__ Cv, int M, int N, int K)
{
    __shared__ __half As[3][128][AS_STRH];
    __shared__ __half Bs[3][16][BS_STRH];

    const int tid  = threadIdx.x;
    const int w    = tid >> 5;
    const int lane = tid & 31;
    const int g    = lane >> 2;
    const int t    = lane & 3;
    const int wm   = (w & 3) * 32;
    const int wn   = (w >> 2) * 64;

    const int mbase = blockIdx.y * 128;
    const int nbase = blockIdx.x * 128;

    const int arow = tid >> 1, acol = (tid & 1) * 8;
    const int brow = tid >> 4, bcol = (tid & 15) * 8;

    const int lrow = (lane & 7) + ((lane >> 3) & 1) * 8;
    const int lcol = (lane >> 4) * 8;
    const int tkrow = (lane & 7) + ((lane >> 3) & 1) * 8;
    const int tncol = (lane >> 4) * 8;

    float acc[2][8][4];
#pragma unroll
    for (int mt = 0; mt < 2; mt++)
#pragma unroll
        for (int nt = 0; nt < 8; nt++)
#pragma unroll
            for (int j = 0; j < 4; j++) acc[mt][nt][j] = 0.f;

    const int NIT = K / 16;

#pragma unroll
    for (int s = 0; s < 2; s++) {
        const int k0 = s * 16;
        cp_async16(&As[s][arow][acol], A + (size_t)(mbase + arow) * K + k0 + acol);
        cp_async16(&Bs[s][brow][bcol], B + (size_t)(k0 + brow) * N + nbase + bcol);
        asm volatile("cp.async.commit_group;");
    }

    int buf = 0;
    for (int it = 0; it < NIT; it++) {
        if (it + 1 < NIT)
            asm volatile("cp.async.wait_group 1;");
        else
            asm volatile("cp.async.wait_group 0;");
        __syncthreads();

        unsigned af[2][4];
#pragma unroll
        for (int mt = 0; mt < 2; mt++)
            ldsm_x4(af[mt][0], af[mt][1], af[mt][2], af[mt][3],
                    &As[buf][wm + mt * 16 + lrow][lcol]);

#pragma unroll
        for (int ntp = 0; ntp < 4; ntp++) {
            unsigned b[4];
            ldsm_x4t(b[0], b[1], b[2], b[3],
                     &Bs[buf][tkrow][wn + ntp * 16 + tncol]);
#pragma unroll
            for (int mt = 0; mt < 2; mt++) {
                mma_f16(acc[mt][2 * ntp][0], acc[mt][2 * ntp][1],
                        acc[mt][2 * ntp][2], acc[mt][2 * ntp][3],
                        af[mt][0], af[mt][1], af[mt][2], af[mt][3], b[0], b[1]);
                mma_f16(acc[mt][2 * ntp + 1][0], acc[mt][2 * ntp + 1][1],
                        acc[mt][2 * ntp + 1][2], acc[mt][2 * ntp + 1][3],
                        af[mt][0], af[mt][1], af[mt][2], af[mt][3], b[2], b[3]);
            }
        }

        if (it + 2 < NIT) {
            const int k0 = (it + 2) * 16;
            const int nb = (it + 2) % 3;
            cp_async16(&As[nb][arow][acol], A + (size_t)(mbase + arow) * K + k0 + acol);
            cp_async16(&Bs[nb][brow][bcol], B + (size_t)(k0 + brow) * N + nbase + bcol);
            asm volatile("cp.async.commit_group;");
        }
        __syncthreads();
        buf = (buf + 1 == 3) ? 0 : buf + 1;
    }

#pragma unroll
    for (int mt = 0; mt < 2; mt++) {
        const int r0 = mbase + wm + mt * 16 + g;
#pragma unroll
        for (int nt = 0; nt < 8; nt++) {
            const int col = nbase + wn + nt * 8 + 2 * t;
            if (OUT_HALF) {
                __half* Ch = (__half*)Cv;
                *(__half2*)(Ch + (size_t)r0 * N + col) =
                    __floats2half2_rn(acc[mt][nt][0], acc[mt][nt][1]);
                *(__half2*)(Ch + (size_t)(r0 + 8) * N + col) =
                    __floats2half2_rn(acc[mt][nt][2], acc[mt][nt][3]);
            } else {
                float* Cf = (float*)Cv;
                *(float2*)(Cf + (size_t)r0 * N + col) =
                    make_float2(acc[mt][nt][0], acc[mt][nt][1]);
                *(float2*)(Cf + (size_t)(r0 + 8) * N + col) =
                    make_float2(acc[mt][nt][2], acc[mt][nt][3]);
            }
        }
    }
}

// ---------------------------------------------------------------------------
// fp16 causal flash attention v2 (FA2 register P-reuse + f16x2 exp2).
// 256 threads / 8 warps / 128 q-rows per phase; two balanced q-tiles/block.
// Q pre-scaled by beta*log2e -> softmax in base-2 domain.
// P stays in registers: S C-frags pack directly into PV A-frags (half2).
// ---------------------------------------------------------------------------
#define KS_STRH 72
#define VS_STRH 72
#define KS_HALVES  (2 * 64 * KS_STRH)
#define VST_HALVES (2 * 64 * VS_STRH)
#define ATTN_SMEM_BYTES ((KS_HALVES + VST_HALVES) * 2)  // 36864 B

__global__ void __launch_bounds__(256, 2) attn_tc_kernel(
    const __half* __restrict__ qk, __half* __restrict__ out)
{
    extern __shared__ __half smh[];
    __half* Ks  = smh;
    __half* VsT = smh + KS_HALVES;

    const int bx = blockIdx.x, h = blockIdx.y, bb = blockIdx.z;
    const int tid  = threadIdx.x;
    const int w    = tid >> 5;
    const int lane = tid & 31;
    const int g    = lane >> 2;
    const int t    = lane & 3;

    const int vd = tid & 63;
    const int vk = (tid >> 6) * 16;

    const __half2 scale2 = __float2half2_rn(BETA_LOG2E);

    const __half* kbase = qk + (size_t)bb * N_TOK * (2 * DIMM) + DIMM + h * DHEAD;

#define FILL_KS(KT, BUF)                                                       \
    {                                                                          \
        _Pragma("unroll")                                                      \
        for (int i = tid; i < 64 * 8; i += 256) {                              \
            int r = i >> 3, c = (i & 7) * 8;                                   \
            cp_async16(&Ks[((BUF) * 64 + r) * KS_STRH + c],                    \
                       kbase + (size_t)((KT) * 64 + r) * (2 * DIMM) + c);      \
        }                                                                      \
        asm volatile("cp.async.commit_group;");                                \
    }
#define LDGV(KT, VREG)                                                         \
    {                                                                          \
        _Pragma("unroll")                                                      \
        for (int j = 0; j < 16; j++)                                           \
            VREG[j] = kbase[(size_t)((KT) * 64 + vk + j) * (2 * DIMM) + vd];   \
    }

    for (int phase = 0; phase < 2; phase++) {
        const int qt = (phase == 0) ? bx : (NQT - 1 - bx);

        const int qrow0 = bb * N_TOK + qt * 128 + w * 16;
        // Q fragments (4 chunks of k16), scaled by beta*log2e
        unsigned qf[4][4];
        {
            const __half* qp  = qk + (size_t)(qrow0 + g) * (2 * DIMM) + h * DHEAD;
            const __half* qp8 = qp + (size_t)8 * (2 * DIMM);
#pragma unroll
            for (int kc = 0; kc < 4; kc++) {
                __half2 a0 = *(const __half2*)(qp  + kc * 16 + 2 * t);
                __half2 a1 = *(const __half2*)(qp8 + kc * 16 + 2 * t);
                __half2 a2 = *(const __half2*)(qp  + kc * 16 + 8 + 2 * t);
                __half2 a3 = *(const __half2*)(qp8 + kc * 16 + 8 + 2 * t);
                qf[kc][0] = h2u(__hmul2(a0, scale2));
                qf[kc][1] = h2u(__hmul2(a1, scale2));
                qf[kc][2] = h2u(__hmul2(a2, scale2));
                qf[kc][3] = h2u(__hmul2(a3, scale2));
            }
        }

        float o[8][4];
#pragma unroll
        for (int nt = 0; nt < 8; nt++)
#pragma unroll
            for (int j = 0; j < 4; j++) o[nt][j] = 0.f;
        float m0 = -1e30f, m1 = -1e30f, l0 = 0.f, l1 = 0.f;

        const int ktmax = 2 * qt + 1;
        const int diagw = 2 * qt + (w >> 2);

        __half vreg[16];
        FILL_KS(0, 0);
        LDGV(0, vreg);

        for (int kt = 0; kt <= ktmax; kt++) {
            const int buf = kt & 1;
            if (kt + 1 <= ktmax) {
                FILL_KS(kt + 1, buf ^ 1);
                asm volatile("cp.async.wait_group 1;");
            } else {
                asm volatile("cp.async.wait_group 0;");
            }

            {
                __half* vrow = &VsT[(buf * 64 + vd) * VS_STRH + vk];
#pragma unroll
                for (int u = 0; u < 8; u++)
                    *(__half2*)(vrow + 2 * u) =
                        __halves2half2(vreg[2 * u], vreg[2 * u + 1]);
            }
            __syncthreads();

            if (kt + 1 <= ktmax) LDGV(kt + 1, vreg);

            if (kt <= diagw) {
                // ---- S = Q @ K^T (base-2-scaled) ----
                float sc[8][4];
#pragma unroll
                for (int nt = 0; nt < 8; nt++) {
                    sc[nt][0] = sc[nt][1] = sc[nt][2] = sc[nt][3] = 0.f;
                    const __half* kr =
                        &Ks[(buf * 64 + nt * 8 + (lane & 7)) * KS_STRH + (lane >> 3) * 8];
                    unsigned b[4];
                    ldsm_x4(b[0], b[1], b[2], b[3], kr);
                    mma_f16(sc[nt][0], sc[nt][1], sc[nt][2], sc[nt][3],
                            qf[0][0], qf[0][1], qf[0][2], qf[0][3], b[0], b[1]);
                    mma_f16(sc[nt][0], sc[nt][1], sc[nt][2], sc[nt][3],
                            qf[1][0], qf[1][1], qf[1][2], qf[1][3], b[2], b[3]);
                    ldsm_x4(b[0], b[1], b[2], b[3], kr + 32);
                    mma_f16(sc[nt][0], sc[nt][1], sc[nt][2], sc[nt][3],
                            qf[2][0], qf[2][1], qf[2][2], qf[2][3], b[0], b[1]);
                    mma_f16(sc[nt][0], sc[nt][1], sc[nt][2], sc[nt][3],
                            qf[3][0], qf[3][1], qf[3][2], qf[3][3], b[2], b[3]);
                }

                // ---- causal mask (warp's diagonal tile only) ----
                if (kt == diagw) {
                    const int lr0 = w * 16 + g, lr1 = lr0 + 8;
                    const int cb  = (w >> 2) * 64;
#pragma unroll
                    for (int nt = 0; nt < 8; nt++) {
                        int col = cb + nt * 8 + 2 * t;
                        if (col     > lr0) sc[nt][0] = -1e30f;
                        if (col + 1 > lr0) sc[nt][1] = -1e30f;
                        if (col     > lr1) sc[nt][2] = -1e30f;
                        if (col + 1 > lr1) sc[nt][3] = -1e30f;
                    }
                }

                // ---- online softmax (base-2) ----
                float tmax0 = -1e30f, tmax1 = -1e30f;
#pragma unroll
                for (int nt = 0; nt < 8; nt++) {
                    tmax0 = fmaxf(tmax0, fmaxf(sc[nt][0], sc[nt][1]));
                    tmax1 = fmaxf(tmax1, fmaxf(sc[nt][2], sc[nt][3]));
                }
                tmax0 = fmaxf(tmax0, __shfl_xor_sync(0xffffffffu, tmax0, 1));
                tmax0 = fmaxf(tmax0, __shfl_xor_sync(0xffffffffu, tmax0, 2));
                tmax1 = fmaxf(tmax1, __shfl_xor_sync(0xffffffffu, tmax1, 1));
                tmax1 = fmaxf(tmax1, __shfl_xor_sync(0xffffffffu, tmax1, 2));

                float mn0 = fmaxf(m0, tmax0), mn1 = fmaxf(m1, tmax1);
                float corr0 = exp2f(m0 - mn0), corr1 = exp2f(m1 - mn1);
                m0 = mn0; m1 = mn1;

                // P = exp2(s - m) via f16x2 MUFU; packed halves ARE PV A-frags.
                unsigned pu0[8], pu1[8];
                float ls0 = 0.f, ls1 = 0.f;
#pragma unroll
                for (int nt = 0; nt < 8; nt++) {
                    __half2 p01 = h2exp2(
                        __floats2half2_rn(sc[nt][0] - mn0, sc[nt][1] - mn0));
                    __half2 p23 = h2exp2(
                        __floats2half2_rn(sc[nt][2] - mn1, sc[nt][3] - mn1));
                    pu0[nt] = h2u(p01);
                    pu1[nt] = h2u(p23);
                    float2 f0 = __half22float2(p01);
                    float2 f1 = __half22float2(p23);
                    ls0 += f0.x + f0.y;
                    ls1 += f1.x + f1.y;
                }
                ls0 += __shfl_xor_sync(0xffffffffu, ls0, 1);
                ls0 += __shfl_xor_sync(0xffffffffu, ls0, 2);
                ls1 += __shfl_xor_sync(0xffffffffu, ls1, 1);
                ls1 += __shfl_xor_sync(0xffffffffu, ls1, 2);
                l0 = l0 * corr0 + ls0;
                l1 = l1 * corr1 + ls1;

#pragma unroll
                for (int nt = 0; nt < 8; nt++) {
                    o[nt][0] *= corr0; o[nt][1] *= corr0;
                    o[nt][2] *= corr1; o[nt][3] *= corr1;
                }

                // ---- O += P @ V : A from registers, B from VsT ldmatrix ----
#pragma unroll
                for (int kc = 0; kc < 4; kc++) {
                    const unsigned a0 = pu0[2 * kc],     a1 = pu1[2 * kc];
                    const unsigned a2 = pu0[2 * kc + 1], a3 = pu1[2 * kc + 1];
#pragma unroll
                    for (int ntp = 0; ntp < 4; ntp++) {
                        unsigned b[4];
                        ldsm_x4(b[0], b[1], b[2], b[3],
                                &VsT[(buf * 64 + ntp * 16 + (lane >> 4) * 8 + (lane & 7))
                                         * VS_STRH
                                     + kc * 16 + ((lane >> 3) & 1) * 8]);
                        mma_f16(o[2 * ntp][0], o[2 * ntp][1],
                                o[2 * ntp][2], o[2 * ntp][3],
                                a0, a1, a2, a3, b[0], b[1]);
                        mma_f16(o[2 * ntp + 1][0], o[2 * ntp + 1][1],
                                o[2 * ntp + 1][2], o[2 * ntp + 1][3],
                                a0, a1, a2, a3, b[2], b[3]);
                    }
                }
            }
            __syncthreads();
        }

        // ---- epilogue: normalize, convert to fp16 (feeds GEMM2) ----
        const float inv0 = 1.f / l0, inv1 = 1.f / l1;
        __half* op0 = out + (size_t)(qrow0 + g) * DIMM + h * DHEAD;
        __half* op1 = op0 + (size_t)8 * DIMM;
#pragma unroll
        for (int nt = 0; nt < 8; nt++) {
            *(__half2*)(op0 + nt * 8 + 2 * t) =
                __floats2half2_rn(o[nt][0] * inv0, o[nt][1] * inv0);
            *(__half2*)(op1 + nt * 8 + 2 * t) =
                __floats2half2_rn(o[nt][2] * inv1, o[nt][3] * inv1);
        }
        __syncthreads();
    }
#undef FILL_KS
#undef LDGV
}

// ---------------------------------------------------------------------------
extern "C" void kernel_launch(void* const* d_in, const int* in_sizes, int n_in,
                              void* d_out, int out_size)
{
    const float* x     = (const float*)d_in[0];
    const float* W_qk  = (const float*)d_in[1];
    const float* W_out = (const float*)d_in[2];
    float* out = (float*)d_out;

    __half *qkh, *aoh, *xh, *wqkh, *woh;
    cudaGetSymbolAddress((void**)&qkh,  g_qkh);
    cudaGetSymbolAddress((void**)&aoh,  g_aoh);
    cudaGetSymbolAddress((void**)&xh,   g_xh);
    cudaGetSymbolAddress((void**)&wqkh, g_wqkh);
    cudaGetSymbolAddress((void**)&woh,  g_woh);

    static bool attr_set = false;
    if (!attr_set) {
        cudaFuncSetAttribute(attn_tc_kernel,
                             cudaFuncAttributeMaxDynamicSharedMemorySize,
                             ATTN_SMEM_BYTES);
        attr_set = true;
    }

    const int nx  = NBATCH * N_TOK * DIMM / 4;
    const int nwq = DIMM * 2 * DIMM / 4;
    const int nwo = DIMM * DIMM / 4;
    const int ntot = nx + nwq + nwo;
    conv3_kernel<<<(ntot + 255) / 256, 256>>>(x, xh, nx, W_qk, wqkh, nwq,
                                              W_out, woh, nwo);

    // qk = x @ W_qk  (fp16 in/out, fp32 accum)
    hgemm_kernel<true><<<dim3((2 * DIMM) / 128, (NBATCH * N_TOK) / 128), 256>>>(
        xh, wqkh, qkh, NBATCH * N_TOK, 2 * DIMM, DIMM);
    // causal attention (fp16, base-2 softmax, register P)
    attn_tc_kernel<<<dim3(NQT / 2, NHEAD, NBATCH), 256, ATTN_SMEM_BYTES>>>(
        qkh, aoh);
    // out = ao @ W_out  (fp16 in, fp32 out)
    hgemm_kernel<false><<<dim3(DIMM / 128, (NBATCH * N_TOK) / 128), 256>>>(
        aoh, woh, out, NBATCH * N_TOK, DIMM, DIMM);
}

// round 15
// speedup vs baseline: 2.2611x; 1.1070x over previous
#include <cuda_runtime.h>
#include <cuda_fp16.h>
#include <math.h>
#include <stdint.h>

#define N_TOK  2048
#define DIMM   1024
#define NBATCH 2
#define NHEAD  16
#define DHEAD  64
#define NQT    (N_TOK / 128)
#define BETA_LOG2E 0.1803368801111244f   /* 0.125 * log2(e) */

// Scratch (static device allocations — no cudaMalloc anywhere)
__device__ __half g_qkh[(size_t)(NBATCH * N_TOK) * (2 * DIMM)];
__device__ __half g_aoh[(size_t)(NBATCH * N_TOK) * DIMM];
__device__ __half g_xh[(size_t)(NBATCH * N_TOK) * DIMM];
__device__ __half g_wqkh[(size_t)DIMM * (2 * DIMM)];
__device__ __half g_woh[(size_t)DIMM * DIMM];

// ---------------------------------------------------------------------------
// helpers
// ---------------------------------------------------------------------------
__device__ __forceinline__ void mma_f16(
    float& c0, float& c1, float& c2, float& c3,
    unsigned a0, unsigned a1, unsigned a2, unsigned a3,
    unsigned b0, unsigned b1)
{
    asm volatile(
        "mma.sync.aligned.m16n8k16.row.col.f32.f16.f16.f32 "
        "{%0,%1,%2,%3}, {%4,%5,%6,%7}, {%8,%9}, {%0,%1,%2,%3};"
        : "+f"(c0), "+f"(c1), "+f"(c2), "+f"(c3)
        : "r"(a0), "r"(a1), "r"(a2), "r"(a3), "r"(b0), "r"(b1));
}

__device__ __forceinline__ void cp_async16(void* smem, const void* gmem) {
    unsigned saddr = (unsigned)__cvta_generic_to_shared(smem);
    asm volatile("cp.async.cg.shared.global [%0], [%1], 16;"
                 :: "r"(saddr), "l"(gmem));
}

__device__ __forceinline__ void ldsm_x4(
    unsigned& r0, unsigned& r1, unsigned& r2, unsigned& r3, const void* p)
{
    unsigned a = (unsigned)__cvta_generic_to_shared(p);
    asm volatile("ldmatrix.sync.aligned.m8n8.x4.shared.b16 {%0,%1,%2,%3}, [%4];"
                 : "=r"(r0), "=r"(r1), "=r"(r2), "=r"(r3) : "r"(a));
}

__device__ __forceinline__ void ldsm_x4t(
    unsigned& r0, unsigned& r1, unsigned& r2, unsigned& r3, const void* p)
{
    unsigned a = (unsigned)__cvta_generic_to_shared(p);
    asm volatile("ldmatrix.sync.aligned.m8n8.x4.trans.shared.b16 {%0,%1,%2,%3}, [%4];"
                 : "=r"(r0), "=r"(r1), "=r"(r2), "=r"(r3) : "r"(a));
}

__device__ __forceinline__ unsigned h2u(__half2 v) {
    return *reinterpret_cast<unsigned*>(&v);
}

// ---------------------------------------------------------------------------
// Fused fp32 -> fp16 convert of x, W_qk, W_out (one launch)
// ---------------------------------------------------------------------------
__global__ void __launch_bounds__(256) conv3_kernel(
    const float* __restrict__ s0, __half* __restrict__ d0, int n0,
    const float* __restrict__ s1, __half* __restrict__ d1, int n1,
    const float* __restrict__ s2, __half* __restrict__ d2, int n2)
{
    int i = blockIdx.x * 256 + threadIdx.x;
    const float* s; __half* d; int j = i;
    if (j < n0)                { s = s0; d = d0; }
    else if ((j -= n0) < n1)   { s = s1; d = d1; }
    else if ((j -= n1) < n2)   { s = s2; d = d2; }
    else return;
    float4 v = ((const float4*)s)[j];
    ((__half2*)d)[2 * j]     = __floats2half2_rn(v.x, v.y);
    ((__half2*)d)[2 * j + 1] = __floats2half2_rn(v.z, v.w);
}

// ---------------------------------------------------------------------------
// fp16 GEMM (unchanged): 128x128 tile, BK=16, 3-stage cp.async.
// ---------------------------------------------------------------------------
#define AS_STRH 24
#define BS_STRH 136

template <bool OUT_HALF>
__global__ void __launch_bounds__(256) hgemm_kernel(
    const __half* __restrict__ A, const __half* __restrict__ B,
    void* __restrict__ Cv, int M, int N, int K)
{
    __shared__ __half As[3][128][AS_STRH];
    __shared__ __half Bs[3][16][BS_STRH];

    const int tid  = threadIdx.x;
    const int w    = tid >> 5;
    const int lane = tid & 31;
    const int g    = lane >> 2;
    const int t    = lane & 3;
    const int wm   = (w & 3) * 32;
    const int wn   = (w >> 2) * 64;

    const int mbase = blockIdx.y * 128;
    const int nbase = blockIdx.x * 128;

    const int arow = tid >> 1, acol = (tid & 1) * 8;
    const int brow = tid >> 4, bcol = (tid & 15) * 8;

    const int lrow = (lane & 7) + ((lane >> 3) & 1) * 8;
    const int lcol = (lane >> 4) * 8;
    const int tkrow = (lane & 7) + ((lane >> 3) & 1) * 8;
    const int tncol = (lane >> 4) * 8;

    float acc[2][8][4];
#pragma unroll
    for (int mt = 0; mt < 2; mt++)
#pragma unroll
        for (int nt = 0; nt < 8; nt++)
#pragma unroll
            for (int j = 0; j < 4; j++) acc[mt][nt][j] = 0.f;

    const int NIT = K / 16;

#pragma unroll
    for (int s = 0; s < 2; s++) {
        const int k0 = s * 16;
        cp_async16(&As[s][arow][acol], A + (size_t)(mbase + arow) * K + k0 + acol);
        cp_async16(&Bs[s][brow][bcol], B + (size_t)(k0 + brow) * N + nbase + bcol);
        asm volatile("cp.async.commit_group;");
    }

    int buf = 0;
    for (int it = 0; it < NIT; it++) {
        if (it + 1 < NIT)
            asm volatile("cp.async.wait_group 1;");
        else
            asm volatile("cp.async.wait_group 0;");
        __syncthreads();

        unsigned af[2][4];
#pragma unroll
        for (int mt = 0; mt < 2; mt++)
            ldsm_x4(af[mt][0], af[mt][1], af[mt][2], af[mt][3],
                    &As[buf][wm + mt * 16 + lrow][lcol]);

#pragma unroll
        for (int ntp = 0; ntp < 4; ntp++) {
            unsigned b[4];
            ldsm_x4t(b[0], b[1], b[2], b[3],
                     &Bs[buf][tkrow][wn + ntp * 16 + tncol]);
#pragma unroll
            for (int mt = 0; mt < 2; mt++) {
                mma_f16(acc[mt][2 * ntp][0], acc[mt][2 * ntp][1],
                        acc[mt][2 * ntp][2], acc[mt][2 * ntp][3],
                        af[mt][0], af[mt][1], af[mt][2], af[mt][3], b[0], b[1]);
                mma_f16(acc[mt][2 * ntp + 1][0], acc[mt][2 * ntp + 1][1],
                        acc[mt][2 * ntp + 1][2], acc[mt][2 * ntp + 1][3],
                        af[mt][0], af[mt][1], af[mt][2], af[mt][3], b[2], b[3]);
            }
        }

        if (it + 2 < NIT) {
            const int k0 = (it + 2) * 16;
            const int nb = (it + 2) % 3;
            cp_async16(&As[nb][arow][acol], A + (size_t)(mbase + arow) * K + k0 + acol);
            cp_async16(&Bs[nb][brow][bcol], B + (size_t)(k0 + brow) * N + nbase + bcol);
            asm volatile("cp.async.commit_group;");
        }
        __syncthreads();
        buf = (buf + 1 == 3) ? 0 : buf + 1;
    }

#pragma unroll
    for (int mt = 0; mt < 2; mt++) {
        const int r0 = mbase + wm + mt * 16 + g;
#pragma unroll
        for (int nt = 0; nt < 8; nt++) {
            const int col = nbase + wn + nt * 8 + 2 * t;
            if (OUT_HALF) {
                __half* Ch = (__half*)Cv;
                *(__half2*)(Ch + (size_t)r0 * N + col) =
                    __floats2half2_rn(acc[mt][nt][0], acc[mt][nt][1]);
                *(__half2*)(Ch + (size_t)(r0 + 8) * N + col) =
                    __floats2half2_rn(acc[mt][nt][2], acc[mt][nt][3]);
            } else {
                float* Cf = (float*)Cv;
                *(float2*)(Cf + (size_t)r0 * N + col) =
                    make_float2(acc[mt][nt][0], acc[mt][nt][1]);
                *(float2*)(Cf + (size_t)(r0 + 8) * N + col) =
                    make_float2(acc[mt][nt][2], acc[mt][nt][3]);
            }
        }
    }
}

// ---------------------------------------------------------------------------
// fp16 causal flash attention v3.
// K tile serves BOTH stages: S via ldmatrix, PV via ldmatrix.trans (no VsT).
// 256 threads / 8 warps / 128 q-rows per phase; balanced q-tile pairs.
// Base-2 softmax; P stays in registers (C-frag == A-frag packing).
// ---------------------------------------------------------------------------
#define KS_STRH 72
#define KS_HALVES (2 * 64 * KS_STRH)
#define ATTN_SMEM_BYTES (KS_HALVES * 2)   // 18432 B

__global__ void __launch_bounds__(256, 2) attn_tc_kernel(
    const __half* __restrict__ qk, __half* __restrict__ out)
{
    extern __shared__ __half smh[];
    __half* Ks = smh;

    const int bx = blockIdx.x, h = blockIdx.y, bb = blockIdx.z;
    const int tid  = threadIdx.x;
    const int w    = tid >> 5;
    const int lane = tid & 31;
    const int g    = lane >> 2;
    const int t    = lane & 3;

    // ldmatrix lane mappings (S-stage normal, PV-stage trans)
    const int srow  = lane & 7;             // S: key-in-8
    const int scol  = (lane >> 3) * 8;      // S: d offset
    const int tkrow = (lane & 7) + ((lane >> 3) & 1) * 8;  // PV: key-in-16
    const int tncol = (lane >> 4) * 8;                     // PV: d offset

    const __half2 scale2 = __float2half2_rn(BETA_LOG2E);

    const __half* kbase = qk + (size_t)bb * N_TOK * (2 * DIMM) + DIMM + h * DHEAD;

#define FILL_KS(KT, BUF)                                                       \
    {                                                                          \
        _Pragma("unroll")                                                      \
        for (int i = tid; i < 64 * 8; i += 256) {                              \
            int r = i >> 3, c = (i & 7) * 8;                                   \
            cp_async16(&Ks[((BUF) * 64 + r) * KS_STRH + c],                    \
                       kbase + (size_t)((KT) * 64 + r) * (2 * DIMM) + c);      \
        }                                                                      \
        asm volatile("cp.async.commit_group;");                                \
    }

    for (int phase = 0; phase < 2; phase++) {
        const int qt = (phase == 0) ? bx : (NQT - 1 - bx);

        const int qrow0 = bb * N_TOK + qt * 128 + w * 16;
        // Q fragments (4 chunks of k16), scaled by beta*log2e
        unsigned qf[4][4];
        {
            const __half* qp  = qk + (size_t)(qrow0 + g) * (2 * DIMM) + h * DHEAD;
            const __half* qp8 = qp + (size_t)8 * (2 * DIMM);
#pragma unroll
            for (int kc = 0; kc < 4; kc++) {
                __half2 a0 = *(const __half2*)(qp  + kc * 16 + 2 * t);
                __half2 a1 = *(const __half2*)(qp8 + kc * 16 + 2 * t);
                __half2 a2 = *(const __half2*)(qp  + kc * 16 + 8 + 2 * t);
                __half2 a3 = *(const __half2*)(qp8 + kc * 16 + 8 + 2 * t);
                qf[kc][0] = h2u(__hmul2(a0, scale2));
                qf[kc][1] = h2u(__hmul2(a1, scale2));
                qf[kc][2] = h2u(__hmul2(a2, scale2));
                qf[kc][3] = h2u(__hmul2(a3, scale2));
            }
        }

        float o[8][4];
#pragma unroll
        for (int nt = 0; nt < 8; nt++)
#pragma unroll
            for (int j = 0; j < 4; j++) o[nt][j] = 0.f;
        float m0 = -1e30f, m1 = -1e30f, l0 = 0.f, l1 = 0.f;

        const int ktmax = 2 * qt + 1;
        const int diagw = 2 * qt + (w >> 2);

        FILL_KS(0, 0);

        for (int kt = 0; kt <= ktmax; kt++) {
            const int buf = kt & 1;
            if (kt + 1 <= ktmax) {
                FILL_KS(kt + 1, buf ^ 1);
                asm volatile("cp.async.wait_group 1;");
            } else {
                asm volatile("cp.async.wait_group 0;");
            }
            __syncthreads();

            if (kt <= diagw) {
                const __half* KsB = Ks + (size_t)buf * 64 * KS_STRH;

                // ---- S = Q @ K^T (base-2-scaled) ----
                float sc[8][4];
#pragma unroll
                for (int nt = 0; nt < 8; nt++) {
                    sc[nt][0] = sc[nt][1] = sc[nt][2] = sc[nt][3] = 0.f;
                    const __half* kr = KsB + (nt * 8 + srow) * KS_STRH + scol;
                    unsigned b[4];
                    ldsm_x4(b[0], b[1], b[2], b[3], kr);
                    mma_f16(sc[nt][0], sc[nt][1], sc[nt][2], sc[nt][3],
                            qf[0][0], qf[0][1], qf[0][2], qf[0][3], b[0], b[1]);
                    mma_f16(sc[nt][0], sc[nt][1], sc[nt][2], sc[nt][3],
                            qf[1][0], qf[1][1], qf[1][2], qf[1][3], b[2], b[3]);
                    ldsm_x4(b[0], b[1], b[2], b[3], kr + 32);
                    mma_f16(sc[nt][0], sc[nt][1], sc[nt][2], sc[nt][3],
                            qf[2][0], qf[2][1], qf[2][2], qf[2][3], b[0], b[1]);
                    mma_f16(sc[nt][0], sc[nt][1], sc[nt][2], sc[nt][3],
                            qf[3][0], qf[3][1], qf[3][2], qf[3][3], b[2], b[3]);
                }

                // ---- causal mask (warp's diagonal tile only) ----
                if (kt == diagw) {
                    const int lr0 = w * 16 + g, lr1 = lr0 + 8;
                    const int cb  = (w >> 2) * 64;
#pragma unroll
                    for (int nt = 0; nt < 8; nt++) {
                        int col = cb + nt * 8 + 2 * t;
                        if (col     > lr0) sc[nt][0] = -1e30f;
                        if (col + 1 > lr0) sc[nt][1] = -1e30f;
                        if (col     > lr1) sc[nt][2] = -1e30f;
                        if (col + 1 > lr1) sc[nt][3] = -1e30f;
                    }
                }

                // ---- online softmax (base-2) ----
                float tmax0 = -1e30f, tmax1 = -1e30f;
#pragma unroll
                for (int nt = 0; nt < 8; nt++) {
                    tmax0 = fmaxf(tmax0, fmaxf(sc[nt][0], sc[nt][1]));
                    tmax1 = fmaxf(tmax1, fmaxf(sc[nt][2], sc[nt][3]));
                }
                tmax0 = fmaxf(tmax0, __shfl_xor_sync(0xffffffffu, tmax0, 1));
                tmax0 = fmaxf(tmax0, __shfl_xor_sync(0xffffffffu, tmax0, 2));
                tmax1 = fmaxf(tmax1, __shfl_xor_sync(0xffffffffu, tmax1, 1));
                tmax1 = fmaxf(tmax1, __shfl_xor_sync(0xffffffffu, tmax1, 2));

                float mn0 = fmaxf(m0, tmax0), mn1 = fmaxf(m1, tmax1);
                float corr0 = exp2f(m0 - mn0), corr1 = exp2f(m1 - mn1);
                m0 = mn0; m1 = mn1;

                // P = exp2(s - m) via f16x2; packed halves ARE the PV A-frags.
                unsigned pu0[8], pu1[8];
                float ls0 = 0.f, ls1 = 0.f;
#pragma unroll
                for (int nt = 0; nt < 8; nt++) {
                    __half2 p01 = h2exp2(
                        __floats2half2_rn(sc[nt][0] - mn0, sc[nt][1] - mn0));
                    __half2 p23 = h2exp2(
                        __floats2half2_rn(sc[nt][2] - mn1, sc[nt][3] - mn1));
                    pu0[nt] = h2u(p01);
                    pu1[nt] = h2u(p23);
                    float2 f0 = __half22float2(p01);
                    float2 f1 = __half22float2(p23);
                    ls0 += f0.x + f0.y;
                    ls1 += f1.x + f1.y;
                }
                ls0 += __shfl_xor_sync(0xffffffffu, ls0, 1);
                ls0 += __shfl_xor_sync(0xffffffffu, ls0, 2);
                ls1 += __shfl_xor_sync(0xffffffffu, ls1, 1);
                ls1 += __shfl_xor_sync(0xffffffffu, ls1, 2);
                l0 = l0 * corr0 + ls0;
                l1 = l1 * corr1 + ls1;

#pragma unroll
                for (int nt = 0; nt < 8; nt++) {
                    o[nt][0] *= corr0; o[nt][1] *= corr0;
                    o[nt][2] *= corr1; o[nt][3] *= corr1;
                }

                // ---- O += P @ V : B-frags via ldmatrix.trans on K tile ----
#pragma unroll
                for (int kc = 0; kc < 4; kc++) {
                    const unsigned a0 = pu0[2 * kc],     a1 = pu1[2 * kc];
                    const unsigned a2 = pu0[2 * kc + 1], a3 = pu1[2 * kc + 1];
                    const __half* vr = KsB + (kc * 16 + tkrow) * KS_STRH + tncol;
#pragma unroll
                    for (int ntp = 0; ntp < 4; ntp++) {
                        unsigned b[4];
                        ldsm_x4t(b[0], b[1], b[2], b[3], vr + ntp * 16);
                        mma_f16(o[2 * ntp][0], o[2 * ntp][1],
                                o[2 * ntp][2], o[2 * ntp][3],
                                a0, a1, a2, a3, b[0], b[1]);
                        mma_f16(o[2 * ntp + 1][0], o[2 * ntp + 1][1],
                                o[2 * ntp + 1][2], o[2 * ntp + 1][3],
                                a0, a1, a2, a3, b[2], b[3]);
                    }
                }
            }
            __syncthreads();
        }

        // ---- epilogue: normalize, convert to fp16 (feeds GEMM2) ----
        const float inv0 = 1.f / l0, inv1 = 1.f / l1;
        __half* op0 = out + (size_t)(qrow0 + g) * DIMM + h * DHEAD;
        __half* op1 = op0 + (size_t)8 * DIMM;
#pragma unroll
        for (int nt = 0; nt < 8; nt++) {
            *(__half2*)(op0 + nt * 8 + 2 * t) =
                __floats2half2_rn(o[nt][0] * inv0, o[nt][1] * inv0);
            *(__half2*)(op1 + nt * 8 + 2 * t) =
                __floats2half2_rn(o[nt][2] * inv1, o[nt][3] * inv1);
        }
        __syncthreads();
    }
#undef FILL_KS
}

// ---------------------------------------------------------------------------
extern "C" void kernel_launch(void* const* d_in, const int* in_sizes, int n_in,
                              void* d_out, int out_size)
{
    const float* x     = (const float*)d_in[0];
    const float* W_qk  = (const float*)d_in[1];
    const float* W_out = (const float*)d_in[2];
    float* out = (float*)d_out;

    __half *qkh, *aoh, *xh, *wqkh, *woh;
    cudaGetSymbolAddress((void**)&qkh,  g_qkh);
    cudaGetSymbolAddress((void**)&aoh,  g_aoh);
    cudaGetSymbolAddress((void**)&xh,   g_xh);
    cudaGetSymbolAddress((void**)&wqkh, g_wqkh);
    cudaGetSymbolAddress((void**)&woh,  g_woh);

    static bool attr_set = false;
    if (!attr_set) {
        cudaFuncSetAttribute(attn_tc_kernel,
                             cudaFuncAttributeMaxDynamicSharedMemorySize,
                             ATTN_SMEM_BYTES);
        attr_set = true;
    }

    const int nx  = NBATCH * N_TOK * DIMM / 4;
    const int nwq = DIMM * 2 * DIMM / 4;
    const int nwo = DIMM * DIMM / 4;
    const int ntot = nx + nwq + nwo;
    conv3_kernel<<<(ntot + 255) / 256, 256>>>(x, xh, nx, W_qk, wqkh, nwq,
                                              W_out, woh, nwo);

    // qk = x @ W_qk  (fp16 in/out, fp32 accum)
    hgemm_kernel<true><<<dim3((2 * DIMM) / 128, (NBATCH * N_TOK) / 128), 256>>>(
        xh, wqkh, qkh, NBATCH * N_TOK, 2 * DIMM, DIMM);
    // causal attention (fp16, base-2 softmax, register P, trans-V from K tile)
    attn_tc_kernel<<<dim3(NQT / 2, NHEAD, NBATCH), 256, ATTN_SMEM_BYTES>>>(
        qkh, aoh);
    // out = ao @ W_out  (fp16 in, fp32 out)
    hgemm_kernel<false><<<dim3(DIMM / 128, (NBATCH * N_TOK) / 128), 256>>>(
        aoh, woh, out, NBATCH * N_TOK, DIMM, DIMM);
}

// round 16
// speedup vs baseline: 2.2839x; 1.0101x over previous
#include <cuda_runtime.h>
#include <cuda_fp16.h>
#include <math.h>
#include <stdint.h>

#define N_TOK  2048
#define DIMM   1024
#define NBATCH 2
#define NHEAD  16
#define DHEAD  64
#define NQT    (N_TOK / 128)
#define BETA_LOG2E 0.1803368801111244f   /* 0.125 * log2(e) */

// Scratch (static device allocations — no cudaMalloc anywhere)
__device__ __half g_qkh[(size_t)(NBATCH * N_TOK) * (2 * DIMM)];
__device__ __half g_aoh[(size_t)(NBATCH * N_TOK) * DIMM];
__device__ __half g_xh[(size_t)(NBATCH * N_TOK) * DIMM];
__device__ __half g_wqkh[(size_t)DIMM * (2 * DIMM)];
__device__ __half g_woh[(size_t)DIMM * DIMM];

// ---------------------------------------------------------------------------
// helpers
// ---------------------------------------------------------------------------
__device__ __forceinline__ void mma_f16(
    float& c0, float& c1, float& c2, float& c3,
    unsigned a0, unsigned a1, unsigned a2, unsigned a3,
    unsigned b0, unsigned b1)
{
    asm volatile(
        "mma.sync.aligned.m16n8k16.row.col.f32.f16.f16.f32 "
        "{%0,%1,%2,%3}, {%4,%5,%6,%7}, {%8,%9}, {%0,%1,%2,%3};"
        : "+f"(c0), "+f"(c1), "+f"(c2), "+f"(c3)
        : "r"(a0), "r"(a1), "r"(a2), "r"(a3), "r"(b0), "r"(b1));
}

__device__ __forceinline__ void cp_async16(void* smem, const void* gmem) {
    unsigned saddr = (unsigned)__cvta_generic_to_shared(smem);
    asm volatile("cp.async.cg.shared.global [%0], [%1], 16;"
                 :: "r"(saddr), "l"(gmem));
}

__device__ __forceinline__ void ldsm_x4(
    unsigned& r0, unsigned& r1, unsigned& r2, unsigned& r3, const void* p)
{
    unsigned a = (unsigned)__cvta_generic_to_shared(p);
    asm volatile("ldmatrix.sync.aligned.m8n8.x4.shared.b16 {%0,%1,%2,%3}, [%4];"
                 : "=r"(r0), "=r"(r1), "=r"(r2), "=r"(r3) : "r"(a));
}

__device__ __forceinline__ void ldsm_x4t(
    unsigned& r0, unsigned& r1, unsigned& r2, unsigned& r3, const void* p)
{
    unsigned a = (unsigned)__cvta_generic_to_shared(p);
    asm volatile("ldmatrix.sync.aligned.m8n8.x4.trans.shared.b16 {%0,%1,%2,%3}, [%4];"
                 : "=r"(r0), "=r"(r1), "=r"(r2), "=r"(r3) : "r"(a));
}

__device__ __forceinline__ unsigned h2u(__half2 v) {
    return *reinterpret_cast<unsigned*>(&v);
}

// ---------------------------------------------------------------------------
// Fused fp32 -> fp16 convert of x, W_qk, W_out (one launch, 2 float4/thread)
// ---------------------------------------------------------------------------
__global__ void __launch_bounds__(256) conv3_kernel(
    const float* __restrict__ s0, __half* __restrict__ d0, int n0,
    const float* __restrict__ s1, __half* __restrict__ d1, int n1,
    const float* __restrict__ s2, __half* __restrict__ d2, int n2)
{
    int base = blockIdx.x * 512 + threadIdx.x;
#pragma unroll
    for (int u = 0; u < 2; u++) {
        int i = base + u * 256;
        const float* s; __half* d; int j = i;
        if (j < n0)                { s = s0; d = d0; }
        else if ((j -= n0) < n1)   { s = s1; d = d1; }
        else if ((j -= n1) < n2)   { s = s2; d = d2; }
        else continue;
        float4 v = ((const float4*)s)[j];
        ((__half2*)d)[2 * j]     = __floats2half2_rn(v.x, v.y);
        ((__half2*)d)[2 * j + 1] = __floats2half2_rn(v.z, v.w);
    }
}

// ---------------------------------------------------------------------------
// fp16 GEMM: 128x128 tile, BK=32, 3-stage cp.async (half the barriers of BK=16).
// A-frags ldmatrix.x4 on [m][k] (stride 40 halves); B-frags ldmatrix.x4.trans.
// ---------------------------------------------------------------------------
#define AS_STRH 40    // halves: 32 data + 8 pad; ldmatrix phases conflict-free
#define BS_STRH 136

template <bool OUT_HALF>
__global__ void __launch_bounds__(256) hgemm_kernel(
    const __half* __restrict__ A, const __half* __restrict__ B,
    void* __restrict__ Cv, int M, int N, int K)
{
    __shared__ __half As[3][128][AS_STRH];
    __shared__ __half Bs[3][32][BS_STRH];

    const int tid  = threadIdx.x;
    const int w    = tid >> 5;
    const int lane = tid & 31;
    const int g    = lane >> 2;
    const int t    = lane & 3;
    const int wm   = (w & 3) * 32;
    const int wn   = (w >> 2) * 64;

    const int mbase = blockIdx.y * 128;
    const int nbase = blockIdx.x * 128;

    // A tile: 128 rows x 4 chunks (8 halves) = 512 chunks, 2/thread
    const int ar0 = tid >> 2,         ac0 = (tid & 3) * 8;
    const int ar1 = (tid + 256) >> 2, ac1 = ((tid + 256) & 3) * 8;
    // B tile: 32 rows x 16 chunks = 512 chunks, 2/thread
    const int br0 = tid >> 4,         bc0 = (tid & 15) * 8;
    const int br1 = (tid + 256) >> 4, bc1 = ((tid + 256) & 15) * 8;

    const int lrow = (lane & 7) + ((lane >> 3) & 1) * 8;
    const int lcol = (lane >> 4) * 8;
    const int tkrow = (lane & 7) + ((lane >> 3) & 1) * 8;
    const int tncol = (lane >> 4) * 8;

    float acc[2][8][4];
#pragma unroll
    for (int mt = 0; mt < 2; mt++)
#pragma unroll
        for (int nt = 0; nt < 8; nt++)
#pragma unroll
            for (int j = 0; j < 4; j++) acc[mt][nt][j] = 0.f;

    const int NIT = K / 32;

#define GLOAD(S, K0)                                                           \
    {                                                                          \
        cp_async16(&As[S][ar0][ac0], A + (size_t)(mbase + ar0) * K + (K0) + ac0); \
        cp_async16(&As[S][ar1][ac1], A + (size_t)(mbase + ar1) * K + (K0) + ac1); \
        cp_async16(&Bs[S][br0][bc0], B + (size_t)((K0) + br0) * N + nbase + bc0); \
        cp_async16(&Bs[S][br1][bc1], B + (size_t)((K0) + br1) * N + nbase + bc1); \
        asm volatile("cp.async.commit_group;");                                \
    }

    GLOAD(0, 0);
    GLOAD(1, 32);

    int buf = 0;
    for (int it = 0; it < NIT; it++) {
        if (it + 1 < NIT)
            asm volatile("cp.async.wait_group 1;");
        else
            asm volatile("cp.async.wait_group 0;");
        __syncthreads();

        unsigned af[2][2][4];   // [kch][mt]
#pragma unroll
        for (int kch = 0; kch < 2; kch++)
#pragma unroll
            for (int mt = 0; mt < 2; mt++)
                ldsm_x4(af[kch][mt][0], af[kch][mt][1], af[kch][mt][2], af[kch][mt][3],
                        &As[buf][wm + mt * 16 + lrow][kch * 16 + lcol]);

#pragma unroll
        for (int kch = 0; kch < 2; kch++) {
#pragma unroll
            for (int ntp = 0; ntp < 4; ntp++) {
                unsigned b[4];
                ldsm_x4t(b[0], b[1], b[2], b[3],
                         &Bs[buf][kch * 16 + tkrow][wn + ntp * 16 + tncol]);
#pragma unroll
                for (int mt = 0; mt < 2; mt++) {
                    mma_f16(acc[mt][2 * ntp][0], acc[mt][2 * ntp][1],
                            acc[mt][2 * ntp][2], acc[mt][2 * ntp][3],
                            af[kch][mt][0], af[kch][mt][1], af[kch][mt][2], af[kch][mt][3],
                            b[0], b[1]);
                    mma_f16(acc[mt][2 * ntp + 1][0], acc[mt][2 * ntp + 1][1],
                            acc[mt][2 * ntp + 1][2], acc[mt][2 * ntp + 1][3],
                            af[kch][mt][0], af[kch][mt][1], af[kch][mt][2], af[kch][mt][3],
                            b[2], b[3]);
                }
            }
        }

        if (it + 2 < NIT) {
            const int nb = (it + 2) % 3;
            GLOAD(nb, (it + 2) * 32);
        }
        __syncthreads();
        buf = (buf + 1 == 3) ? 0 : buf + 1;
    }
#undef GLOAD

#pragma unroll
    for (int mt = 0; mt < 2; mt++) {
        const int r0 = mbase + wm + mt * 16 + g;
#pragma unroll
        for (int nt = 0; nt < 8; nt++) {
            const int col = nbase + wn + nt * 8 + 2 * t;
            if (OUT_HALF) {
                __half* Ch = (__half*)Cv;
                *(__half2*)(Ch + (size_t)r0 * N + col) =
                    __floats2half2_rn(acc[mt][nt][0], acc[mt][nt][1]);
                *(__half2*)(Ch + (size_t)(r0 + 8) * N + col) =
                    __floats2half2_rn(acc[mt][nt][2], acc[mt][nt][3]);
            } else {
                float* Cf = (float*)Cv;
                *(float2*)(Cf + (size_t)r0 * N + col) =
                    make_float2(acc[mt][nt][0], acc[mt][nt][1]);
                *(float2*)(Cf + (size_t)(r0 + 8) * N + col) =
                    make_float2(acc[mt][nt][2], acc[mt][nt][3]);
            }
        }
    }
}

// ---------------------------------------------------------------------------
// fp16 causal flash attention v4: 128-key double-buffered stages (two 64-key
// compute sub-passes per barrier pair). K tile serves S (ldmatrix) and PV
// (ldmatrix.trans). Base-2 softmax; P stays in registers.
// ---------------------------------------------------------------------------
#define KS_STRH 72
#define KS_HALVES (2 * 128 * KS_STRH)
#define ATTN_SMEM_BYTES (KS_HALVES * 2)   // 36864 B

__global__ void __launch_bounds__(256, 2) attn_tc_kernel(
    const __half* __restrict__ qk, __half* __restrict__ out)
{
    extern __shared__ __half smh[];
    __half* Ks = smh;

    const int bx = blockIdx.x, h = blockIdx.y, bb = blockIdx.z;
    const int tid  = threadIdx.x;
    const int w    = tid >> 5;
    const int lane = tid & 31;
    const int g    = lane >> 2;
    const int t    = lane & 3;

    const int srow  = lane & 7;
    const int scol  = (lane >> 3) * 8;
    const int tkrow = (lane & 7) + ((lane >> 3) & 1) * 8;
    const int tncol = (lane >> 4) * 8;

    const __half2 scale2 = __float2half2_rn(BETA_LOG2E);

    const __half* kbase = qk + (size_t)bb * N_TOK * (2 * DIMM) + DIMM + h * DHEAD;

    // Fill one 128-key stage (pair of 64-key tiles): 1024 chunks, 4/thread.
#define FILL_KP(P, BUF)                                                        \
    {                                                                          \
        _Pragma("unroll")                                                      \
        for (int i = tid; i < 128 * 8; i += 256) {                             \
            int r = i >> 3, c = (i & 7) * 8;                                   \
            cp_async16(&Ks[((BUF) * 128 + r) * KS_STRH + c],                   \
                       kbase + (size_t)((P) * 128 + r) * (2 * DIMM) + c);      \
        }                                                                      \
        asm volatile("cp.async.commit_group;");                                \
    }

    for (int phase = 0; phase < 2; phase++) {
        const int qt = (phase == 0) ? bx : (NQT - 1 - bx);

        const int qrow0 = bb * N_TOK + qt * 128 + w * 16;
        unsigned qf[4][4];
        {
            const __half* qp  = qk + (size_t)(qrow0 + g) * (2 * DIMM) + h * DHEAD;
            const __half* qp8 = qp + (size_t)8 * (2 * DIMM);
#pragma unroll
            for (int kc = 0; kc < 4; kc++) {
                __half2 a0 = *(const __half2*)(qp  + kc * 16 + 2 * t);
                __half2 a1 = *(const __half2*)(qp8 + kc * 16 + 2 * t);
                __half2 a2 = *(const __half2*)(qp  + kc * 16 + 8 + 2 * t);
                __half2 a3 = *(const __half2*)(qp8 + kc * 16 + 8 + 2 * t);
                qf[kc][0] = h2u(__hmul2(a0, scale2));
                qf[kc][1] = h2u(__hmul2(a1, scale2));
                qf[kc][2] = h2u(__hmul2(a2, scale2));
                qf[kc][3] = h2u(__hmul2(a3, scale2));
            }
        }

        float o[8][4];
#pragma unroll
        for (int nt = 0; nt < 8; nt++)
#pragma unroll
            for (int j = 0; j < 4; j++) o[nt][j] = 0.f;
        float m0 = -1e30f, m1 = -1e30f, l0 = 0.f, l1 = 0.f;

        const int diagw = 2 * qt + (w >> 2);
        const int npair = qt + 1;           // 128-key pairs (covers 2qt+2 tiles)

        FILL_KP(0, 0);

        for (int p = 0; p < npair; p++) {
            const int buf = p & 1;
            if (p + 1 < npair) {
                FILL_KP(p + 1, buf ^ 1);
                asm volatile("cp.async.wait_group 1;");
            } else {
                asm volatile("cp.async.wait_group 0;");
            }
            __syncthreads();

#pragma unroll
            for (int sub = 0; sub < 2; sub++) {
                const int kt = 2 * p + sub;
                if (kt > diagw) continue;
                const __half* KsB = Ks + ((size_t)buf * 128 + sub * 64) * KS_STRH;

                // ---- S = Q @ K^T (base-2-scaled) ----
                float sc[8][4];
#pragma unroll
                for (int nt = 0; nt < 8; nt++) {
                    sc[nt][0] = sc[nt][1] = sc[nt][2] = sc[nt][3] = 0.f;
                    const __half* kr = KsB + (nt * 8 + srow) * KS_STRH + scol;
                    unsigned b[4];
                    ldsm_x4(b[0], b[1], b[2], b[3], kr);
                    mma_f16(sc[nt][0], sc[nt][1], sc[nt][2], sc[nt][3],
                            qf[0][0], qf[0][1], qf[0][2], qf[0][3], b[0], b[1]);
                    mma_f16(sc[nt][0], sc[nt][1], sc[nt][2], sc[nt][3],
                            qf[1][0], qf[1][1], qf[1][2], qf[1][3], b[2], b[3]);
                    ldsm_x4(b[0], b[1], b[2], b[3], kr + 32);
                    mma_f16(sc[nt][0], sc[nt][1], sc[nt][2], sc[nt][3],
                            qf[2][0], qf[2][1], qf[2][2], qf[2][3], b[0], b[1]);
                    mma_f16(sc[nt][0], sc[nt][1], sc[nt][2], sc[nt][3],
                            qf[3][0], qf[3][1], qf[3][2], qf[3][3], b[2], b[3]);
                }

                // ---- causal mask (warp's diagonal tile only) ----
                if (kt == diagw) {
                    const int lr0 = w * 16 + g, lr1 = lr0 + 8;
                    const int cb  = (w >> 2) * 64;
#pragma unroll
                    for (int nt = 0; nt < 8; nt++) {
                        int col = cb + nt * 8 + 2 * t;
                        if (col     > lr0) sc[nt][0] = -1e30f;
                        if (col + 1 > lr0) sc[nt][1] = -1e30f;
                        if (col     > lr1) sc[nt][2] = -1e30f;
                        if (col + 1 > lr1) sc[nt][3] = -1e30f;
                    }
                }

                // ---- online softmax (base-2) ----
                float tmax0 = -1e30f, tmax1 = -1e30f;
#pragma unroll
                for (int nt = 0; nt < 8; nt++) {
                    tmax0 = fmaxf(tmax0, fmaxf(sc[nt][0], sc[nt][1]));
                    tmax1 = fmaxf(tmax1, fmaxf(sc[nt][2], sc[nt][3]));
                }
                tmax0 = fmaxf(tmax0, __shfl_xor_sync(0xffffffffu, tmax0, 1));
                tmax0 = fmaxf(tmax0, __shfl_xor_sync(0xffffffffu, tmax0, 2));
                tmax1 = fmaxf(tmax1, __shfl_xor_sync(0xffffffffu, tmax1, 1));
                tmax1 = fmaxf(tmax1, __shfl_xor_sync(0xffffffffu, tmax1, 2));

                float mn0 = fmaxf(m0, tmax0), mn1 = fmaxf(m1, tmax1);
                float corr0 = exp2f(m0 - mn0), corr1 = exp2f(m1 - mn1);
                m0 = mn0; m1 = mn1;

                unsigned pu0[8], pu1[8];
                float ls0 = 0.f, ls1 = 0.f;
#pragma unroll
                for (int nt = 0; nt < 8; nt++) {
                    __half2 p01 = h2exp2(
                        __floats2half2_rn(sc[nt][0] - mn0, sc[nt][1] - mn0));
                    __half2 p23 = h2exp2(
                        __floats2half2_rn(sc[nt][2] - mn1, sc[nt][3] - mn1));
                    pu0[nt] = h2u(p01);
                    pu1[nt] = h2u(p23);
                    float2 f0 = __half22float2(p01);
                    float2 f1 = __half22float2(p23);
                    ls0 += f0.x + f0.y;
                    ls1 += f1.x + f1.y;
                }
                ls0 += __shfl_xor_sync(0xffffffffu, ls0, 1);
                ls0 += __shfl_xor_sync(0xffffffffu, ls0, 2);
                ls1 += __shfl_xor_sync(0xffffffffu, ls1, 1);
                ls1 += __shfl_xor_sync(0xffffffffu, ls1, 2);
                l0 = l0 * corr0 + ls0;
                l1 = l1 * corr1 + ls1;

#pragma unroll
                for (int nt = 0; nt < 8; nt++) {
                    o[nt][0] *= corr0; o[nt][1] *= corr0;
                    o[nt][2] *= corr1; o[nt][3] *= corr1;
                }

                // ---- O += P @ V (B-frags via ldmatrix.trans on K tile) ----
#pragma unroll
                for (int kc = 0; kc < 4; kc++) {
                    const unsigned a0 = pu0[2 * kc],     a1 = pu1[2 * kc];
                    const unsigned a2 = pu0[2 * kc + 1], a3 = pu1[2 * kc + 1];
                    const __half* vr = KsB + (kc * 16 + tkrow) * KS_STRH + tncol;
#pragma unroll
                    for (int ntp = 0; ntp < 4; ntp++) {
                        unsigned b[4];
                        ldsm_x4t(b[0], b[1], b[2], b[3], vr + ntp * 16);
                        mma_f16(o[2 * ntp][0], o[2 * ntp][1],
                                o[2 * ntp][2], o[2 * ntp][3],
                                a0, a1, a2, a3, b[0], b[1]);
                        mma_f16(o[2 * ntp + 1][0], o[2 * ntp + 1][1],
                                o[2 * ntp + 1][2], o[2 * ntp + 1][3],
                                a0, a1, a2, a3, b[2], b[3]);
                    }
                }
            }
            __syncthreads();
        }

        // ---- epilogue: normalize, convert to fp16 (feeds GEMM2) ----
        const float inv0 = 1.f / l0, inv1 = 1.f / l1;
        __half* op0 = out + (size_t)(qrow0 + g) * DIMM + h * DHEAD;
        __half* op1 = op0 + (size_t)8 * DIMM;
#pragma unroll
        for (int nt = 0; nt < 8; nt++) {
            *(__half2*)(op0 + nt * 8 + 2 * t) =
                __floats2half2_rn(o[nt][0] * inv0, o[nt][1] * inv0);
            *(__half2*)(op1 + nt * 8 + 2 * t) =
                __floats2half2_rn(o[nt][2] * inv1, o[nt][3] * inv1);
        }
        __syncthreads();
    }
#undef FILL_KP
}

// ---------------------------------------------------------------------------
extern "C" void kernel_launch(void* const* d_in, const int* in_sizes, int n_in,
                              void* d_out, int out_size)
{
    const float* x     = (const float*)d_in[0];
    const float* W_qk  = (const float*)d_in[1];
    const float* W_out = (const float*)d_in[2];
    float* out = (float*)d_out;

    __half *qkh, *aoh, *xh, *wqkh, *woh;
    cudaGetSymbolAddress((void**)&qkh,  g_qkh);
    cudaGetSymbolAddress((void**)&aoh,  g_aoh);
    cudaGetSymbolAddress((void**)&xh,   g_xh);
    cudaGetSymbolAddress((void**)&wqkh, g_wqkh);
    cudaGetSymbolAddress((void**)&woh,  g_woh);

    static bool attr_set = false;
    if (!attr_set) {
        cudaFuncSetAttribute(attn_tc_kernel,
                             cudaFuncAttributeMaxDynamicSharedMemorySize,
                             ATTN_SMEM_BYTES);
        attr_set = true;
    }

    const int nx  = NBATCH * N_TOK * DIMM / 4;
    const int nwq = DIMM * 2 * DIMM / 4;
    const int nwo = DIMM * DIMM / 4;
    const int ntot = nx + nwq + nwo;
    conv3_kernel<<<(ntot + 511) / 512, 256>>>(x, xh, nx, W_qk, wqkh, nwq,
                                              W_out, woh, nwo);

    // qk = x @ W_qk  (fp16 in/out, fp32 accum)
    hgemm_kernel<true><<<dim3((2 * DIMM) / 128, (NBATCH * N_TOK) / 128), 256>>>(
        xh, wqkh, qkh, NBATCH * N_TOK, 2 * DIMM, DIMM);
    // causal attention (fp16, base-2 softmax, register P, 128-key stages)
    attn_tc_kernel<<<dim3(NQT / 2, NHEAD, NBATCH), 256, ATTN_SMEM_BYTES>>>(
        qkh, aoh);
    // out = ao @ W_out  (fp16 in, fp32 out)
    hgemm_kernel<false><<<dim3(DIMM / 128, (NBATCH * N_TOK) / 128), 256>>>(
        aoh, woh, out, NBATCH * N_TOK, DIMM, DIMM);
}